// round 7
// baseline (speedup 1.0000x reference)
#include <cuda_runtime.h>
#include <cuda_bf16.h>
#include <math.h>
#include <stdint.h>

#define SEQ    2048
#define HDIM   2048
#define NH     16
#define DN     128
#define DR     64
#define DV     128
#define QL     1536
#define KL     512
#define DFULL  192
#define FUSED_NPAD 2176
#define FUSED_REAL 2112
#define QB_N   3072
#define KVB_N  4096
#define KP_H   6144
#define KP_QL  4608
#define KP_KL  1536
#define KP_D   576
#define KP_SEQ 6144

// ---------------- device scratch (zero-initialized) ----------------
__device__ float g_fused[SEQ * FUSED_NPAD];
__device__ float g_qp[SEQ * QB_N];
__device__ float g_kvp[SEQ * KVB_N];
__device__ float g_Sc[NH * SEQ * SEQ];
__device__ float g_attn[SEQ * HDIM];
__device__ __nv_bfloat16 g_H3   [SEQ * KP_H];
__device__ __nv_bfloat16 g_QN3  [SEQ * KP_QL];
__device__ __nv_bfloat16 g_KVN3 [SEQ * KP_KL];
__device__ __nv_bfloat16 g_ATTN3[SEQ * KP_H];
__device__ __nv_bfloat16 g_WKVA3[FUSED_NPAD * KP_H];   // rows >= 2112 stay 0
__device__ __nv_bfloat16 g_WQB3 [QB_N * KP_QL];
__device__ __nv_bfloat16 g_WKVB3[KVB_N * KP_KL];
__device__ __nv_bfloat16 g_WO3  [HDIM * KP_H];
__device__ __nv_bfloat16 g_Q3 [NH * SEQ * KP_D];
__device__ __nv_bfloat16 g_K3 [NH * SEQ * KP_D];
__device__ __nv_bfloat16 g_V3 [NH * DV * KP_SEQ];      // [h][d][3s]
__device__ __nv_bfloat16 g_P3 [NH * SEQ * KP_SEQ];     // tail (k>q) stays 0

// ---------------- helpers ----------------
__device__ __forceinline__ void bf_split(float x, __nv_bfloat16& hi, __nv_bfloat16& lo) {
    hi = __float2bfloat16(x);
    lo = __float2bfloat16(x - __bfloat162float(hi));
}
__device__ __forceinline__ uint32_t smem_u32(const void* p) {
    uint32_t a;
    asm("{ .reg .u64 t; cvta.to.shared.u64 t, %1; cvt.u32.u64 %0, t; }" : "=r"(a) : "l"(p));
    return a;
}
__device__ __forceinline__ void cp16(uint32_t dst, const void* src) {
    asm volatile("cp.async.cg.shared.global [%0], [%1], 16;" :: "r"(dst), "l"(src));
}
__device__ __forceinline__ void ldsm_x4(uint32_t* r, uint32_t a) {
    asm volatile("ldmatrix.sync.aligned.m8n8.x4.shared.b16 {%0,%1,%2,%3}, [%4];"
                 : "=r"(r[0]), "=r"(r[1]), "=r"(r[2]), "=r"(r[3]) : "r"(a));
}
__device__ __forceinline__ void mma16816(float* c, const uint32_t* a, uint32_t b0, uint32_t b1) {
    asm volatile(
        "mma.sync.aligned.m16n8k16.row.col.f32.bf16.bf16.f32 "
        "{%0,%1,%2,%3}, {%4,%5,%6,%7}, {%8,%9}, {%0,%1,%2,%3};"
        : "+f"(c[0]), "+f"(c[1]), "+f"(c[2]), "+f"(c[3])
        : "r"(a[0]), "r"(a[1]), "r"(a[2]), "r"(a[3]), "r"(b0), "r"(b1));
}

// ============================================================================
// bf16 GEMM: C[m,n] = sum_k' A[m,k'] B[n,k'] (both K'-major bf16, C fp32)
// Tile 128x128, BK'=64, 128 threads (4 warps, warp tile 64x64),
// 3-stage cp.async pipeline, ldmatrix.x4 for A and B.
// mode 0: plain; 1: skip n0 > m0+127; 2: k'-tiles limited to 3*(m0+128).
// ============================================================================
#define GSMEM (3 * 32768)

__global__ __launch_bounds__(128) void gemm_bf16(
    const __nv_bfloat16* __restrict__ A, long long sA,
    const __nv_bfloat16* __restrict__ B, long long sB,
    float* __restrict__ C, long long sC,
    int lda, int ldb, int ldc, int Kp, int mode)
{
    const int n0 = blockIdx.x * 128;
    const int m0 = blockIdx.y * 128;
    if (mode == 1 && n0 > m0 + 127) return;
    A += (size_t)blockIdx.z * sA;
    B += (size_t)blockIdx.z * sB;
    C += (size_t)blockIdx.z * sC;

    int ntiles = Kp >> 6;
    if (mode == 2) {
        int lim = (3 * (m0 + 128)) >> 6;
        if (lim < ntiles) ntiles = lim;
    }

    extern __shared__ char smraw[];
    const uint32_t s0 = smem_u32(smraw);   // stage s: A at s*32768, B at +16384

    const int tid = threadIdx.x;
    const int lane = tid & 31;
    const int wid = tid >> 5;
    const int wm = (wid & 1) * 64;
    const int wn = (wid >> 1) * 64;
    const int l7 = lane & 7;
    const int g = lane >> 2, t4 = lane & 3;

    const int r16 = lane & 15;             // row within 16-row tile
    const int seg = (lane >> 4) & 1;       // k-seg select
    uint32_t a_off[4], b_off[4];
#pragma unroll
    for (int mt = 0; mt < 4; mt++) a_off[mt] = (uint32_t)((wm + mt * 16 + r16) * 128);
#pragma unroll
    for (int nt = 0; nt < 4; nt++) b_off[nt] = (uint32_t)((wn + nt * 16 + r16) * 128);

    float c[4][8][4];
#pragma unroll
    for (int i = 0; i < 4; i++)
#pragma unroll
        for (int j = 0; j < 8; j++)
#pragma unroll
            for (int e = 0; e < 4; e++) c[i][j][e] = 0.f;

    // ---- async tile loader: 128 rows x 64 bf16 for A and B (one commit group) ----
    auto load_tile = [&](int i, int buf) {
        const __nv_bfloat16* Ag = A + (size_t)m0 * lda + (i << 6);
        const __nv_bfloat16* Bg = B + (size_t)n0 * ldb + (i << 6);
        const uint32_t da = s0 + buf * 32768;
        const uint32_t db = da + 16384;
#pragma unroll
        for (int t = 0; t < 8; t++) {
            int ch = tid + t * 128;               // 0..1023
            int r = ch >> 3;                      // row 0..127
            int s = ch & 7;                       // 16B seg 0..7
            uint32_t sw = (uint32_t)(r * 128 + ((s ^ (r & 7)) << 4));
            cp16(da + sw, Ag + (size_t)r * lda + s * 8);
            cp16(db + sw, Bg + (size_t)r * ldb + s * 8);
        }
        asm volatile("cp.async.commit_group;");
    };

    load_tile(0, 0);
    if (ntiles > 1) load_tile(1, 1); else asm volatile("cp.async.commit_group;");

    for (int i = 0; i < ntiles; i++) {
        if (i + 2 < ntiles) load_tile(i + 2, (i + 2) % 3);
        else asm volatile("cp.async.commit_group;");
        asm volatile("cp.async.wait_group 2;");
        __syncthreads();

        const uint32_t ab = s0 + (i % 3) * 32768;
        const uint32_t bb = ab + 16384;
#pragma unroll
        for (int kc = 0; kc < 4; kc++) {
            const uint32_t xx = (uint32_t)(((kc * 2 + seg) ^ l7) << 4);
            uint32_t a[4][4], b[4][4];
#pragma unroll
            for (int mt = 0; mt < 4; mt++) ldsm_x4(a[mt], ab + a_off[mt] + xx);
#pragma unroll
            for (int nt = 0; nt < 4; nt++) ldsm_x4(b[nt], bb + b_off[nt] + xx);
#pragma unroll
            for (int mt = 0; mt < 4; mt++)
#pragma unroll
                for (int nt = 0; nt < 4; nt++) {
                    mma16816(c[mt][2 * nt],     a[mt], b[nt][0], b[nt][2]);
                    mma16816(c[mt][2 * nt + 1], a[mt], b[nt][1], b[nt][3]);
                }
        }
        __syncthreads();
    }

    // epilogue
#pragma unroll
    for (int mt = 0; mt < 4; mt++)
#pragma unroll
        for (int nt = 0; nt < 8; nt++) {
            int row = m0 + wm + mt * 16 + g;
            int col = n0 + wn + nt * 8 + t4 * 2;
            *(float2*)&C[(size_t)row * ldc + col] = make_float2(c[mt][nt][0], c[mt][nt][1]);
            *(float2*)&C[(size_t)(row + 8) * ldc + col] = make_float2(c[mt][nt][2], c[mt][nt][3]);
        }
}

// ---------------- activation split (A-side: hi,hi,lo) ----------------
__global__ __launch_bounds__(256) void split_act(
    const float* __restrict__ X, __nv_bfloat16* __restrict__ X3, int total)
{
    int i = blockIdx.x * 256 + threadIdx.x;
    if (i >= total) return;
    __nv_bfloat16 hi, lo;
    bf_split(X[i], hi, lo);
    __nv_bfloat16* o = X3 + 3 * (size_t)i;
    o[0] = hi; o[1] = hi; o[2] = lo;
}

// ---------------- weight transpose+split: W[K,N] -> W3t[N][3K] (B-side: hi,lo,hi) ----------------
__global__ __launch_bounds__(1024) void transpose_split_w(
    const float* __restrict__ W, __nv_bfloat16* __restrict__ W3t, int K, int N)
{
    __shared__ float t[32][33];
    const int kb = blockIdx.x * 32, nb = blockIdx.y * 32;
    const int tx = threadIdx.x & 31, ty = threadIdx.x >> 5;
    t[ty][tx] = W[(size_t)(kb + ty) * N + nb + tx];
    __syncthreads();
    __nv_bfloat16 hi, lo;
    bf_split(t[tx][ty], hi, lo);
    __nv_bfloat16* o = W3t + (size_t)(nb + ty) * (3 * K) + 3 * (kb + tx);
    o[0] = hi; o[1] = lo; o[2] = hi;
}

// ---------------- RMSNorm + split (A-side) ----------------
__global__ __launch_bounds__(256) void rmsnorm_split(
    const float* __restrict__ src, const float* __restrict__ gamma,
    __nv_bfloat16* __restrict__ dst3, int stride, int len)
{
    const int row = blockIdx.x;
    const float* x = src + (size_t)row * stride;
    float ss = 0.f;
    for (int i = threadIdx.x; i < len; i += 256) { float v = x[i]; ss += v * v; }
#pragma unroll
    for (int o = 16; o; o >>= 1) ss += __shfl_xor_sync(0xffffffffu, ss, o);
    __shared__ float ws[8]; __shared__ float s_inv;
    if ((threadIdx.x & 31) == 0) ws[threadIdx.x >> 5] = ss;
    __syncthreads();
    if (threadIdx.x == 0) {
        float t = 0.f;
#pragma unroll
        for (int i = 0; i < 8; i++) t += ws[i];
        s_inv = rsqrtf(t / (float)len + 1e-6f);
    }
    __syncthreads();
    const float inv = s_inv;
    __nv_bfloat16* out = dst3 + (size_t)row * 3 * len;
    for (int i = threadIdx.x; i < len; i += 256) {
        __nv_bfloat16 hi, lo;
        bf_split(x[i] * gamma[i] * inv, hi, lo);
        out[3 * i] = hi; out[3 * i + 1] = hi; out[3 * i + 2] = lo;
    }
}

// ---------------- RoPE + pack + split ----------------
__global__ __launch_bounds__(192) void rope_pack_split(
    const float* __restrict__ qp, const float* __restrict__ kvp,
    const float* __restrict__ fused,
    __nv_bfloat16* __restrict__ Q3, __nv_bfloat16* __restrict__ K3,
    __nv_bfloat16* __restrict__ V3)
{
    const int s = blockIdx.x, h = blockIdx.y, d = threadIdx.x;
    const float scale = 0.07216878364870323f; // 1/sqrt(192)
    float qv, kv;
    if (d < DN) {
        qv = qp[(size_t)s * QB_N + h * DFULL + d] * scale;
        kv = kvp[(size_t)s * KVB_N + h * (DN + DV) + d];
        float vv = kvp[(size_t)s * KVB_N + h * (DN + DV) + DN + d];
        __nv_bfloat16 hi, lo;
        bf_split(vv, hi, lo);
        __nv_bfloat16* vp = V3 + ((size_t)h * DV + d) * KP_SEQ + 3 * s;
        vp[0] = hi; vp[1] = lo; vp[2] = hi;   // B-side
    } else {
        int j = d - DN, i = j & 31;
        float inv_freq = powf(10000.f, -(float)(2 * i) / 64.f);
        float sn, cs;
        sincosf((float)s * inv_freq, &sn, &cs);
        size_t qoff = (size_t)s * QB_N + h * DFULL + DN;
        float qpe = qp[qoff + j];
        float qrot = (j < 32) ? -qp[qoff + j + 32] : qp[qoff + j - 32];
        size_t koff = (size_t)s * FUSED_NPAD + (QL + KL);
        float kpe = fused[koff + j];
        float krot = (j < 32) ? -fused[koff + j + 32] : fused[koff + j - 32];
        qv = (qpe * cs + qrot * sn) * scale;
        kv = kpe * cs + krot * sn;
    }
    __nv_bfloat16 qhi, qlo, khi, klo;
    bf_split(qv, qhi, qlo);
    bf_split(kv, khi, klo);
    __nv_bfloat16* qo = Q3 + ((size_t)h * SEQ + s) * KP_D + 3 * d;
    qo[0] = qhi; qo[1] = qhi; qo[2] = qlo;    // A-side
    __nv_bfloat16* ko = K3 + ((size_t)h * SEQ + s) * KP_D + 3 * d;
    ko[0] = khi; ko[1] = klo; ko[2] = khi;    // B-side
}

// ---------------- causal softmax + split (A-side); tail stays zero ----------------
__global__ __launch_bounds__(256) void softmax_split(
    const float* __restrict__ Sc, __nv_bfloat16* __restrict__ P3)
{
    const int q = blockIdx.x, h = blockIdx.y, tid = threadIdx.x;
    const float* row = Sc + ((size_t)h * SEQ + q) * SEQ;
    __nv_bfloat16* out = P3 + ((size_t)h * SEQ + q) * KP_SEQ;
    const int n = q + 1;
    __shared__ float red[8]; __shared__ float bc;

    float mx = -INFINITY;
    for (int i = tid; i < n; i += 256) mx = fmaxf(mx, row[i]);
#pragma unroll
    for (int o = 16; o; o >>= 1) mx = fmaxf(mx, __shfl_xor_sync(0xffffffffu, mx, o));
    if ((tid & 31) == 0) red[tid >> 5] = mx;
    __syncthreads();
    if (tid == 0) {
        float m = red[0];
#pragma unroll
        for (int i = 1; i < 8; i++) m = fmaxf(m, red[i]);
        bc = m;
    }
    __syncthreads();
    const float M = bc;
    float sm = 0.f;
    for (int i = tid; i < n; i += 256) sm += __expf(row[i] - M);
#pragma unroll
    for (int o = 16; o; o >>= 1) sm += __shfl_xor_sync(0xffffffffu, sm, o);
    if ((tid & 31) == 0) red[tid >> 5] = sm;
    __syncthreads();
    if (tid == 0) {
        float t = 0.f;
#pragma unroll
        for (int i = 0; i < 8; i++) t += red[i];
        bc = 1.f / t;
    }
    __syncthreads();
    const float inv = bc;
    for (int i = tid; i < n; i += 256) {
        __nv_bfloat16 hi, lo;
        bf_split(__expf(row[i] - M) * inv, hi, lo);
        out[3 * i] = hi; out[3 * i + 1] = hi; out[3 * i + 2] = lo;
    }
}

// ---------------- launcher ----------------
extern "C" void kernel_launch(void* const* d_in, const int* in_sizes, int n_in,
                              void* d_out, int out_size)
{
    const float* hidden     = (const float*)d_in[0];
    const float* w_kv_a     = (const float*)d_in[1];
    const float* q_a_gamma  = (const float*)d_in[2];
    const float* w_qb       = (const float*)d_in[3];
    const float* kv_a_gamma = (const float*)d_in[4];
    const float* w_kvb      = (const float*)d_in[5];
    const float* w_o        = (const float*)d_in[6];
    float* out = (float*)d_out;

    static float *fused = nullptr, *qp, *kvp, *Sc, *attn;
    static __nv_bfloat16 *H3, *QN3, *KVN3, *ATTN3, *WKVA3, *WQB3, *WKVB3, *WO3, *Q3, *K3, *V3, *P3;
    if (!fused) {
        cudaGetSymbolAddress((void**)&fused, g_fused);
        cudaGetSymbolAddress((void**)&qp,    g_qp);
        cudaGetSymbolAddress((void**)&kvp,   g_kvp);
        cudaGetSymbolAddress((void**)&Sc,    g_Sc);
        cudaGetSymbolAddress((void**)&attn,  g_attn);
        cudaGetSymbolAddress((void**)&H3,    g_H3);
        cudaGetSymbolAddress((void**)&QN3,   g_QN3);
        cudaGetSymbolAddress((void**)&KVN3,  g_KVN3);
        cudaGetSymbolAddress((void**)&ATTN3, g_ATTN3);
        cudaGetSymbolAddress((void**)&WKVA3, g_WKVA3);
        cudaGetSymbolAddress((void**)&WQB3,  g_WQB3);
        cudaGetSymbolAddress((void**)&WKVB3, g_WKVB3);
        cudaGetSymbolAddress((void**)&WO3,   g_WO3);
        cudaGetSymbolAddress((void**)&Q3,    g_Q3);
        cudaGetSymbolAddress((void**)&K3,    g_K3);
        cudaGetSymbolAddress((void**)&V3,    g_V3);
        cudaGetSymbolAddress((void**)&P3,    g_P3);
        cudaFuncSetAttribute(gemm_bf16, cudaFuncAttributeMaxDynamicSharedMemorySize, GSMEM);
    }

    // operand preparation
    split_act<<<(SEQ * HDIM + 255) / 256, 256>>>(hidden, H3, SEQ * HDIM);
    transpose_split_w<<<dim3(HDIM / 32, FUSED_REAL / 32), 1024>>>(w_kv_a, WKVA3, HDIM, FUSED_REAL);
    transpose_split_w<<<dim3(QL / 32, QB_N / 32), 1024>>>(w_qb, WQB3, QL, QB_N);
    transpose_split_w<<<dim3(KL / 32, KVB_N / 32), 1024>>>(w_kvb, WKVB3, KL, KVB_N);
    transpose_split_w<<<dim3(HDIM / 32, HDIM / 32), 1024>>>(w_o, WO3, HDIM, HDIM);

    // 1) fused = hidden @ w_kv_a
    gemm_bf16<<<dim3(FUSED_NPAD / 128, SEQ / 128), 128, GSMEM>>>(
        H3, 0, WKVA3, 0, fused, 0, KP_H, KP_H, FUSED_NPAD, KP_H, 0);

    // 2) rmsnorm + split
    rmsnorm_split<<<SEQ, 256>>>(fused, q_a_gamma, QN3, FUSED_NPAD, QL);
    rmsnorm_split<<<SEQ, 256>>>(fused + QL, kv_a_gamma, KVN3, FUSED_NPAD, KL);

    // 3) projections
    gemm_bf16<<<dim3(QB_N / 128, SEQ / 128), 128, GSMEM>>>(
        QN3, 0, WQB3, 0, qp, 0, KP_QL, KP_QL, QB_N, KP_QL, 0);
    gemm_bf16<<<dim3(KVB_N / 128, SEQ / 128), 128, GSMEM>>>(
        KVN3, 0, WKVB3, 0, kvp, 0, KP_KL, KP_KL, KVB_N, KP_KL, 0);

    // 4) rope + pack + split
    rope_pack_split<<<dim3(SEQ, NH), 192>>>(qp, kvp, fused, Q3, K3, V3);

    // 5) scores = Q @ K^T (causal block-skip), per head
    gemm_bf16<<<dim3(SEQ / 128, SEQ / 128, NH), 128, GSMEM>>>(
        Q3, (long long)SEQ * KP_D, K3, (long long)SEQ * KP_D,
        Sc, (long long)SEQ * SEQ, KP_D, KP_D, SEQ, KP_D, 1);

    // 6) softmax + split
    softmax_split<<<dim3(SEQ, NH), 256>>>(Sc, P3);

    // 7) attn = P @ V (causal k-limit), per head
    gemm_bf16<<<dim3(1, SEQ / 128, NH), 128, GSMEM>>>(
        P3, (long long)SEQ * KP_SEQ, V3, (long long)DV * KP_SEQ,
        attn, (long long)DV, KP_SEQ, KP_SEQ, NH * DV, KP_SEQ, 2);

    // 8) out = attn @ w_o
    split_act<<<(SEQ * HDIM + 255) / 256, 256>>>(attn, ATTN3, SEQ * HDIM);
    gemm_bf16<<<dim3(HDIM / 128, SEQ / 128), 128, GSMEM>>>(
        ATTN3, 0, WO3, 0, out, 0, KP_H, KP_H, HDIM, KP_H, 0);
}

// round 8
// speedup vs baseline: 1.0898x; 1.0898x over previous
#include <cuda_runtime.h>
#include <cuda_bf16.h>
#include <math.h>
#include <stdint.h>

#define SEQ    2048
#define HDIM   2048
#define NH     16
#define DN     128
#define DR     64
#define DV     128
#define QL     1536
#define KL     512
#define DFULL  192
#define FUSED_NPAD 2176
#define FUSED_REAL 2112
#define QB_N   3072
#define KVB_N  4096
#define KP_H   6144
#define KP_QL  4608
#define KP_KL  1536
#define KP_D   576
#define KP_SEQ 6144

// ---------------- device scratch (zero-initialized) ----------------
__device__ float g_fused[SEQ * FUSED_NPAD];
__device__ float g_qp[SEQ * QB_N];
__device__ float g_kvp[SEQ * KVB_N];
__device__ float g_Sc[NH * SEQ * SEQ];
__device__ float g_attn[SEQ * HDIM];
__device__ __nv_bfloat16 g_H3   [SEQ * KP_H];
__device__ __nv_bfloat16 g_QN3  [SEQ * KP_QL];
__device__ __nv_bfloat16 g_KVN3 [SEQ * KP_KL];
__device__ __nv_bfloat16 g_ATTN3[SEQ * KP_H];
__device__ __nv_bfloat16 g_WKVA3[FUSED_NPAD * KP_H];   // rows >= 2112 stay 0
__device__ __nv_bfloat16 g_WQB3 [QB_N * KP_QL];
__device__ __nv_bfloat16 g_WKVB3[KVB_N * KP_KL];
__device__ __nv_bfloat16 g_WO3  [HDIM * KP_H];
__device__ __nv_bfloat16 g_Q3 [NH * SEQ * KP_D];
__device__ __nv_bfloat16 g_K3 [NH * SEQ * KP_D];
__device__ __nv_bfloat16 g_V3 [NH * DV * KP_SEQ];      // [h][d][3s]
__device__ __nv_bfloat16 g_P3 [NH * SEQ * KP_SEQ];     // tail (k>q) stays 0

// ---------------- helpers ----------------
__device__ __forceinline__ void bf_split(float x, __nv_bfloat16& hi, __nv_bfloat16& lo) {
    hi = __float2bfloat16(x);
    lo = __float2bfloat16(x - __bfloat162float(hi));
}
__device__ __forceinline__ uint32_t smem_u32(const void* p) {
    uint32_t a;
    asm("{ .reg .u64 t; cvta.to.shared.u64 t, %1; cvt.u32.u64 %0, t; }" : "=r"(a) : "l"(p));
    return a;
}
__device__ __forceinline__ void cp16(uint32_t dst, const void* src) {
    asm volatile("cp.async.cg.shared.global [%0], [%1], 16;" :: "r"(dst), "l"(src));
}
__device__ __forceinline__ void ldsm_x4(uint32_t* r, uint32_t a) {
    asm volatile("ldmatrix.sync.aligned.m8n8.x4.shared.b16 {%0,%1,%2,%3}, [%4];"
                 : "=r"(r[0]), "=r"(r[1]), "=r"(r[2]), "=r"(r[3]) : "r"(a));
}
__device__ __forceinline__ void mma16816(float* c, const uint32_t* a, uint32_t b0, uint32_t b1) {
    asm volatile(
        "mma.sync.aligned.m16n8k16.row.col.f32.bf16.bf16.f32 "
        "{%0,%1,%2,%3}, {%4,%5,%6,%7}, {%8,%9}, {%0,%1,%2,%3};"
        : "+f"(c[0]), "+f"(c[1]), "+f"(c[2]), "+f"(c[3])
        : "r"(a[0]), "r"(a[1]), "r"(a[2]), "r"(a[3]), "r"(b0), "r"(b1));
}

// ============================================================================
// bf16 GEMM: C[m,n] = sum_k' A[m,k'] B[n,k'] (both K'-major bf16, C fp32)
// Tile 128x128, BK'=64, 256 threads (8 warps, warp tile 64x32),
// 3-stage cp.async pipeline, ldmatrix.x4 for A and B (B: 2 x4 per k-step).
// mode 0: plain; 1: skip n0 > m0+127; 2: k'-tiles limited to 3*(m0+128).
// ============================================================================
#define GSMEM (3 * 32768)

__global__ __launch_bounds__(256) void gemm_bf16(
    const __nv_bfloat16* __restrict__ A, long long sA,
    const __nv_bfloat16* __restrict__ B, long long sB,
    float* __restrict__ C, long long sC,
    int lda, int ldb, int ldc, int Kp, int mode)
{
    const int n0 = blockIdx.x * 128;
    const int m0 = blockIdx.y * 128;
    if (mode == 1 && n0 > m0 + 127) return;
    A += (size_t)blockIdx.z * sA;
    B += (size_t)blockIdx.z * sB;
    C += (size_t)blockIdx.z * sC;

    int ntiles = Kp >> 6;
    if (mode == 2) {
        int lim = (3 * (m0 + 128)) >> 6;
        if (lim < ntiles) ntiles = lim;
    }

    extern __shared__ char smraw[];
    const uint32_t s0 = smem_u32(smraw);   // stage s: A at s*32768, B at +16384

    const int tid = threadIdx.x;
    const int lane = tid & 31;
    const int wid = tid >> 5;
    const int wm = (wid & 1) * 64;
    const int wn = (wid >> 1) * 32;
    const int g = lane >> 2, t4 = lane & 3;

    // A ldmatrix addressing (x4: 16 rows x 2 k-segs)
    const int ra = lane & 15;
    const int sega = (lane >> 4) & 1;
    // B ldmatrix addressing (x4 covers 2 n-slabs x 2 k-segs)
    const int rb = (lane >> 4) * 8 + (lane & 7);   // row within 16-row pair
    const int segb = (lane >> 3) & 1;
    uint32_t a_off[4], b_off[2];
#pragma unroll
    for (int mt = 0; mt < 4; mt++) a_off[mt] = (uint32_t)((wm + mt * 16 + ra) * 128);
#pragma unroll
    for (int p = 0; p < 2; p++) b_off[p] = (uint32_t)((wn + p * 16 + rb) * 128);
    const int a_swrow = ra & 7;
    const int b_swrow = rb & 7;

    float c[4][4][4];
#pragma unroll
    for (int i = 0; i < 4; i++)
#pragma unroll
        for (int j = 0; j < 4; j++)
#pragma unroll
            for (int e = 0; e < 4; e++) c[i][j][e] = 0.f;

    // ---- async tile loader: 128 rows x 64 bf16 for A and B (one commit group) ----
    auto load_tile = [&](int i, int buf) {
        const __nv_bfloat16* Ag = A + (size_t)m0 * lda + (i << 6);
        const __nv_bfloat16* Bg = B + (size_t)n0 * ldb + (i << 6);
        const uint32_t da = s0 + buf * 32768;
        const uint32_t db = da + 16384;
#pragma unroll
        for (int t = 0; t < 4; t++) {
            int ch = tid + t * 256;               // 0..1023
            int r = ch >> 3;                      // row 0..127
            int s = ch & 7;                       // 16B seg 0..7
            uint32_t sw = (uint32_t)(r * 128 + ((s ^ (r & 7)) << 4));
            cp16(da + sw, Ag + (size_t)r * lda + s * 8);
            cp16(db + sw, Bg + (size_t)r * ldb + s * 8);
        }
        asm volatile("cp.async.commit_group;");
    };

    load_tile(0, 0);
    if (ntiles > 1) load_tile(1, 1); else asm volatile("cp.async.commit_group;");

    for (int i = 0; i < ntiles; i++) {
        if (i + 2 < ntiles) load_tile(i + 2, (i + 2) % 3);
        else asm volatile("cp.async.commit_group;");
        asm volatile("cp.async.wait_group 2;");
        __syncthreads();

        const uint32_t ab = s0 + (i % 3) * 32768;
        const uint32_t bb = ab + 16384;
#pragma unroll
        for (int kc = 0; kc < 4; kc++) {
            const uint32_t ax = (uint32_t)(((kc * 2 + sega) ^ a_swrow) << 4);
            const uint32_t bx = (uint32_t)(((kc * 2 + segb) ^ b_swrow) << 4);
            uint32_t a[4][4], b[2][4];
#pragma unroll
            for (int mt = 0; mt < 4; mt++) ldsm_x4(a[mt], ab + a_off[mt] + ax);
#pragma unroll
            for (int p = 0; p < 2; p++) ldsm_x4(b[p], bb + b_off[p] + bx);
#pragma unroll
            for (int mt = 0; mt < 4; mt++) {
                mma16816(c[mt][0], a[mt], b[0][0], b[0][1]);
                mma16816(c[mt][1], a[mt], b[0][2], b[0][3]);
                mma16816(c[mt][2], a[mt], b[1][0], b[1][1]);
                mma16816(c[mt][3], a[mt], b[1][2], b[1][3]);
            }
        }
        __syncthreads();
    }

    // epilogue
#pragma unroll
    for (int mt = 0; mt < 4; mt++)
#pragma unroll
        for (int nt = 0; nt < 4; nt++) {
            int row = m0 + wm + mt * 16 + g;
            int col = n0 + wn + nt * 8 + t4 * 2;
            *(float2*)&C[(size_t)row * ldc + col] = make_float2(c[mt][nt][0], c[mt][nt][1]);
            *(float2*)&C[(size_t)(row + 8) * ldc + col] = make_float2(c[mt][nt][2], c[mt][nt][3]);
        }
}

// ---------------- activation split (A-side: hi,hi,lo) ----------------
__global__ __launch_bounds__(256) void split_act(
    const float* __restrict__ X, __nv_bfloat16* __restrict__ X3, int total)
{
    int i = blockIdx.x * 256 + threadIdx.x;
    if (i >= total) return;
    __nv_bfloat16 hi, lo;
    bf_split(X[i], hi, lo);
    __nv_bfloat16* o = X3 + 3 * (size_t)i;
    o[0] = hi; o[1] = hi; o[2] = lo;
}

// ---------------- weight transpose+split: W[K,N] -> W3t[N][3K] (B-side: hi,lo,hi) ----------------
__global__ __launch_bounds__(1024) void transpose_split_w(
    const float* __restrict__ W, __nv_bfloat16* __restrict__ W3t, int K, int N)
{
    __shared__ float t[32][33];
    const int kb = blockIdx.x * 32, nb = blockIdx.y * 32;
    const int tx = threadIdx.x & 31, ty = threadIdx.x >> 5;
    t[ty][tx] = W[(size_t)(kb + ty) * N + nb + tx];
    __syncthreads();
    __nv_bfloat16 hi, lo;
    bf_split(t[tx][ty], hi, lo);
    __nv_bfloat16* o = W3t + (size_t)(nb + ty) * (3 * K) + 3 * (kb + tx);
    o[0] = hi; o[1] = lo; o[2] = hi;
}

// ---------------- RMSNorm + split (A-side) ----------------
__global__ __launch_bounds__(256) void rmsnorm_split(
    const float* __restrict__ src, const float* __restrict__ gamma,
    __nv_bfloat16* __restrict__ dst3, int stride, int len)
{
    const int row = blockIdx.x;
    const float* x = src + (size_t)row * stride;
    float ss = 0.f;
    for (int i = threadIdx.x; i < len; i += 256) { float v = x[i]; ss += v * v; }
#pragma unroll
    for (int o = 16; o; o >>= 1) ss += __shfl_xor_sync(0xffffffffu, ss, o);
    __shared__ float ws[8]; __shared__ float s_inv;
    if ((threadIdx.x & 31) == 0) ws[threadIdx.x >> 5] = ss;
    __syncthreads();
    if (threadIdx.x == 0) {
        float t = 0.f;
#pragma unroll
        for (int i = 0; i < 8; i++) t += ws[i];
        s_inv = rsqrtf(t / (float)len + 1e-6f);
    }
    __syncthreads();
    const float inv = s_inv;
    __nv_bfloat16* out = dst3 + (size_t)row * 3 * len;
    for (int i = threadIdx.x; i < len; i += 256) {
        __nv_bfloat16 hi, lo;
        bf_split(x[i] * gamma[i] * inv, hi, lo);
        out[3 * i] = hi; out[3 * i + 1] = hi; out[3 * i + 2] = lo;
    }
}

// ---------------- RoPE + pack + split ----------------
__global__ __launch_bounds__(192) void rope_pack_split(
    const float* __restrict__ qp, const float* __restrict__ kvp,
    const float* __restrict__ fused,
    __nv_bfloat16* __restrict__ Q3, __nv_bfloat16* __restrict__ K3,
    __nv_bfloat16* __restrict__ V3)
{
    const int s = blockIdx.x, h = blockIdx.y, d = threadIdx.x;
    const float scale = 0.07216878364870323f; // 1/sqrt(192)
    float qv, kv;
    if (d < DN) {
        qv = qp[(size_t)s * QB_N + h * DFULL + d] * scale;
        kv = kvp[(size_t)s * KVB_N + h * (DN + DV) + d];
        float vv = kvp[(size_t)s * KVB_N + h * (DN + DV) + DN + d];
        __nv_bfloat16 hi, lo;
        bf_split(vv, hi, lo);
        __nv_bfloat16* vp = V3 + ((size_t)h * DV + d) * KP_SEQ + 3 * s;
        vp[0] = hi; vp[1] = lo; vp[2] = hi;   // B-side
    } else {
        int j = d - DN, i = j & 31;
        float inv_freq = powf(10000.f, -(float)(2 * i) / 64.f);
        float sn, cs;
        sincosf((float)s * inv_freq, &sn, &cs);
        size_t qoff = (size_t)s * QB_N + h * DFULL + DN;
        float qpe = qp[qoff + j];
        float qrot = (j < 32) ? -qp[qoff + j + 32] : qp[qoff + j - 32];
        size_t koff = (size_t)s * FUSED_NPAD + (QL + KL);
        float kpe = fused[koff + j];
        float krot = (j < 32) ? -fused[koff + j + 32] : fused[koff + j - 32];
        qv = (qpe * cs + qrot * sn) * scale;
        kv = kpe * cs + krot * sn;
    }
    __nv_bfloat16 qhi, qlo, khi, klo;
    bf_split(qv, qhi, qlo);
    bf_split(kv, khi, klo);
    __nv_bfloat16* qo = Q3 + ((size_t)h * SEQ + s) * KP_D + 3 * d;
    qo[0] = qhi; qo[1] = qhi; qo[2] = qlo;    // A-side
    __nv_bfloat16* ko = K3 + ((size_t)h * SEQ + s) * KP_D + 3 * d;
    ko[0] = khi; ko[1] = klo; ko[2] = khi;    // B-side
}

// ---------------- causal softmax + split (A-side); tail stays zero ----------------
__global__ __launch_bounds__(256) void softmax_split(
    const float* __restrict__ Sc, __nv_bfloat16* __restrict__ P3)
{
    const int q = blockIdx.x, h = blockIdx.y, tid = threadIdx.x;
    const float* row = Sc + ((size_t)h * SEQ + q) * SEQ;
    __nv_bfloat16* out = P3 + ((size_t)h * SEQ + q) * KP_SEQ;
    const int n = q + 1;
    __shared__ float red[8]; __shared__ float bc;

    float mx = -INFINITY;
    for (int i = tid; i < n; i += 256) mx = fmaxf(mx, row[i]);
#pragma unroll
    for (int o = 16; o; o >>= 1) mx = fmaxf(mx, __shfl_xor_sync(0xffffffffu, mx, o));
    if ((tid & 31) == 0) red[tid >> 5] = mx;
    __syncthreads();
    if (tid == 0) {
        float m = red[0];
#pragma unroll
        for (int i = 1; i < 8; i++) m = fmaxf(m, red[i]);
        bc = m;
    }
    __syncthreads();
    const float M = bc;
    float sm = 0.f;
    for (int i = tid; i < n; i += 256) sm += __expf(row[i] - M);
#pragma unroll
    for (int o = 16; o; o >>= 1) sm += __shfl_xor_sync(0xffffffffu, sm, o);
    if ((tid & 31) == 0) red[tid >> 5] = sm;
    __syncthreads();
    if (tid == 0) {
        float t = 0.f;
#pragma unroll
        for (int i = 0; i < 8; i++) t += red[i];
        bc = 1.f / t;
    }
    __syncthreads();
    const float inv = bc;
    for (int i = tid; i < n; i += 256) {
        __nv_bfloat16 hi, lo;
        bf_split(__expf(row[i] - M) * inv, hi, lo);
        out[3 * i] = hi; out[3 * i + 1] = hi; out[3 * i + 2] = lo;
    }
}

// ---------------- launcher ----------------
extern "C" void kernel_launch(void* const* d_in, const int* in_sizes, int n_in,
                              void* d_out, int out_size)
{
    const float* hidden     = (const float*)d_in[0];
    const float* w_kv_a     = (const float*)d_in[1];
    const float* q_a_gamma  = (const float*)d_in[2];
    const float* w_qb       = (const float*)d_in[3];
    const float* kv_a_gamma = (const float*)d_in[4];
    const float* w_kvb      = (const float*)d_in[5];
    const float* w_o        = (const float*)d_in[6];
    float* out = (float*)d_out;

    static float *fused = nullptr, *qp, *kvp, *Sc, *attn;
    static __nv_bfloat16 *H3, *QN3, *KVN3, *ATTN3, *WKVA3, *WQB3, *WKVB3, *WO3, *Q3, *K3, *V3, *P3;
    if (!fused) {
        cudaGetSymbolAddress((void**)&fused, g_fused);
        cudaGetSymbolAddress((void**)&qp,    g_qp);
        cudaGetSymbolAddress((void**)&kvp,   g_kvp);
        cudaGetSymbolAddress((void**)&Sc,    g_Sc);
        cudaGetSymbolAddress((void**)&attn,  g_attn);
        cudaGetSymbolAddress((void**)&H3,    g_H3);
        cudaGetSymbolAddress((void**)&QN3,   g_QN3);
        cudaGetSymbolAddress((void**)&KVN3,  g_KVN3);
        cudaGetSymbolAddress((void**)&ATTN3, g_ATTN3);
        cudaGetSymbolAddress((void**)&WKVA3, g_WKVA3);
        cudaGetSymbolAddress((void**)&WQB3,  g_WQB3);
        cudaGetSymbolAddress((void**)&WKVB3, g_WKVB3);
        cudaGetSymbolAddress((void**)&WO3,   g_WO3);
        cudaGetSymbolAddress((void**)&Q3,    g_Q3);
        cudaGetSymbolAddress((void**)&K3,    g_K3);
        cudaGetSymbolAddress((void**)&V3,    g_V3);
        cudaGetSymbolAddress((void**)&P3,    g_P3);
        cudaFuncSetAttribute(gemm_bf16, cudaFuncAttributeMaxDynamicSharedMemorySize, GSMEM);
    }

    // operand preparation
    split_act<<<(SEQ * HDIM + 255) / 256, 256>>>(hidden, H3, SEQ * HDIM);
    transpose_split_w<<<dim3(HDIM / 32, FUSED_REAL / 32), 1024>>>(w_kv_a, WKVA3, HDIM, FUSED_REAL);
    transpose_split_w<<<dim3(QL / 32, QB_N / 32), 1024>>>(w_qb, WQB3, QL, QB_N);
    transpose_split_w<<<dim3(KL / 32, KVB_N / 32), 1024>>>(w_kvb, WKVB3, KL, KVB_N);
    transpose_split_w<<<dim3(HDIM / 32, HDIM / 32), 1024>>>(w_o, WO3, HDIM, HDIM);

    // 1) fused = hidden @ w_kv_a
    gemm_bf16<<<dim3(FUSED_NPAD / 128, SEQ / 128), 256, GSMEM>>>(
        H3, 0, WKVA3, 0, fused, 0, KP_H, KP_H, FUSED_NPAD, KP_H, 0);

    // 2) rmsnorm + split
    rmsnorm_split<<<SEQ, 256>>>(fused, q_a_gamma, QN3, FUSED_NPAD, QL);
    rmsnorm_split<<<SEQ, 256>>>(fused + QL, kv_a_gamma, KVN3, FUSED_NPAD, KL);

    // 3) projections
    gemm_bf16<<<dim3(QB_N / 128, SEQ / 128), 256, GSMEM>>>(
        QN3, 0, WQB3, 0, qp, 0, KP_QL, KP_QL, QB_N, KP_QL, 0);
    gemm_bf16<<<dim3(KVB_N / 128, SEQ / 128), 256, GSMEM>>>(
        KVN3, 0, WKVB3, 0, kvp, 0, KP_KL, KP_KL, KVB_N, KP_KL, 0);

    // 4) rope + pack + split
    rope_pack_split<<<dim3(SEQ, NH), 192>>>(qp, kvp, fused, Q3, K3, V3);

    // 5) scores = Q @ K^T (causal block-skip), per head
    gemm_bf16<<<dim3(SEQ / 128, SEQ / 128, NH), 256, GSMEM>>>(
        Q3, (long long)SEQ * KP_D, K3, (long long)SEQ * KP_D,
        Sc, (long long)SEQ * SEQ, KP_D, KP_D, SEQ, KP_D, 1);

    // 6) softmax + split
    softmax_split<<<dim3(SEQ, NH), 256>>>(Sc, P3);

    // 7) attn = P @ V (causal k-limit), per head
    gemm_bf16<<<dim3(1, SEQ / 128, NH), 256, GSMEM>>>(
        P3, (long long)SEQ * KP_SEQ, V3, (long long)DV * KP_SEQ,
        attn, (long long)DV, KP_SEQ, KP_SEQ, NH * DV, KP_SEQ, 2);

    // 8) out = attn @ w_o
    split_act<<<(SEQ * HDIM + 255) / 256, 256>>>(attn, ATTN3, SEQ * HDIM);
    gemm_bf16<<<dim3(HDIM / 128, SEQ / 128), 256, GSMEM>>>(
        ATTN3, 0, WO3, 0, out, 0, KP_H, KP_H, HDIM, KP_H, 0);
}

// round 9
// speedup vs baseline: 1.5389x; 1.4121x over previous
#include <cuda_runtime.h>
#include <cuda_fp16.h>
#include <math.h>
#include <stdint.h>

#define SEQ    2048
#define HDIM   2048
#define NH     16
#define DN     128
#define DR     64
#define DV     128
#define QL     1536
#define KL     512
#define DFULL  192
#define FUSED_NPAD 2176
#define FUSED_REAL 2112
#define QB_N   3072
#define KVB_N  4096
// 2x k-expansion (fp16 Markidis: A=(hi,lo), B=(hi,hi))
#define K2_H   4096
#define K2_QL  3072
#define K2_KL  1024
#define K2_D   384
#define K2_SEQ 4096

// ---------------- device scratch (zero-initialized) ----------------
__device__ float g_fused[SEQ * FUSED_NPAD];
__device__ float g_qp[SEQ * QB_N];
__device__ float g_kvp[SEQ * KVB_N];
__device__ float g_Sc[NH * SEQ * SEQ];
__device__ float g_attn[SEQ * HDIM];
__device__ __half g_H3   [SEQ * K2_H];
__device__ __half g_QN3  [SEQ * K2_QL];
__device__ __half g_KVN3 [SEQ * K2_KL];
__device__ __half g_ATTN3[SEQ * K2_H];
__device__ __half g_WKVA3[FUSED_NPAD * K2_H];   // rows >= 2112 stay 0
__device__ __half g_WQB3 [QB_N * K2_QL];
__device__ __half g_WKVB3[KVB_N * K2_KL];
__device__ __half g_WO3  [HDIM * K2_H];
__device__ __half g_Q3 [NH * SEQ * K2_D];
__device__ __half g_K3 [NH * SEQ * K2_D];
__device__ __half g_V3 [NH * DV * K2_SEQ];      // [h][d][2s]
__device__ __half g_P3 [NH * SEQ * K2_SEQ];     // tail (k>q) stays 0

// ---------------- helpers ----------------
__device__ __forceinline__ void h_split(float x, __half& hi, __half& lo) {
    hi = __float2half_rn(x);
    lo = __float2half_rn(x - __half2float(hi));
}
__device__ __forceinline__ uint32_t smem_u32(const void* p) {
    uint32_t a;
    asm("{ .reg .u64 t; cvta.to.shared.u64 t, %1; cvt.u32.u64 %0, t; }" : "=r"(a) : "l"(p));
    return a;
}
__device__ __forceinline__ void cp16(uint32_t dst, const void* src) {
    asm volatile("cp.async.cg.shared.global [%0], [%1], 16;" :: "r"(dst), "l"(src));
}
__device__ __forceinline__ void ldsm_x4(uint32_t* r, uint32_t a) {
    asm volatile("ldmatrix.sync.aligned.m8n8.x4.shared.b16 {%0,%1,%2,%3}, [%4];"
                 : "=r"(r[0]), "=r"(r[1]), "=r"(r[2]), "=r"(r[3]) : "r"(a));
}
__device__ __forceinline__ void mma16816(float* c, const uint32_t* a, uint32_t b0, uint32_t b1) {
    asm volatile(
        "mma.sync.aligned.m16n8k16.row.col.f32.f16.f16.f32 "
        "{%0,%1,%2,%3}, {%4,%5,%6,%7}, {%8,%9}, {%0,%1,%2,%3};"
        : "+f"(c[0]), "+f"(c[1]), "+f"(c[2]), "+f"(c[3])
        : "r"(a[0]), "r"(a[1]), "r"(a[2]), "r"(a[3]), "r"(b0), "r"(b1));
}

// ============================================================================
// fp16 GEMM: C[m,n] = sum_k'' A[m,k''] B[n,k''] (both K''-major fp16, C fp32)
// Tile 128x128, BK''=64, 256 threads (8 warps, warp tile 64x32),
// 3-stage cp.async pipeline (single barrier per chunk), ldmatrix.x4.
// mode 0: plain; 1: skip n0 > m0+127; 2: k''-tiles limited to 2*(m0+128).
// ============================================================================
#define GSMEM (3 * 32768)

__global__ __launch_bounds__(256) void gemm_fp16(
    const __half* __restrict__ A, long long sA,
    const __half* __restrict__ B, long long sB,
    float* __restrict__ C, long long sC,
    int lda, int ldb, int ldc, int Kp, int mode)
{
    const int n0 = blockIdx.x * 128;
    const int m0 = blockIdx.y * 128;
    if (mode == 1 && n0 > m0 + 127) return;
    A += (size_t)blockIdx.z * sA;
    B += (size_t)blockIdx.z * sB;
    C += (size_t)blockIdx.z * sC;

    int ntiles = Kp >> 6;
    if (mode == 2) {
        int lim = (2 * (m0 + 128)) >> 6;
        if (lim < ntiles) ntiles = lim;
    }

    extern __shared__ char smraw[];
    const uint32_t s0 = smem_u32(smraw);   // stage s: A at s*32768, B at +16384

    const int tid = threadIdx.x;
    const int lane = tid & 31;
    const int wid = tid >> 5;
    const int wm = (wid & 1) * 64;
    const int wn = (wid >> 1) * 32;
    const int g = lane >> 2, t4 = lane & 3;

    // A ldmatrix addressing (x4: 16 rows x 2 k-segs)
    const int ra = lane & 15;
    const int sega = (lane >> 4) & 1;
    // B ldmatrix addressing (x4 covers 2 n-slabs x 2 k-segs)
    const int rb = (lane >> 4) * 8 + (lane & 7);
    const int segb = (lane >> 3) & 1;
    uint32_t a_off[4], b_off[2];
#pragma unroll
    for (int mt = 0; mt < 4; mt++) a_off[mt] = (uint32_t)((wm + mt * 16 + ra) * 128);
#pragma unroll
    for (int p = 0; p < 2; p++) b_off[p] = (uint32_t)((wn + p * 16 + rb) * 128);
    const int a_swrow = ra & 7;
    const int b_swrow = rb & 7;

    float c[4][4][4];
#pragma unroll
    for (int i = 0; i < 4; i++)
#pragma unroll
        for (int j = 0; j < 4; j++)
#pragma unroll
            for (int e = 0; e < 4; e++) c[i][j][e] = 0.f;

    auto load_tile = [&](int i, int buf) {
        const __half* Ag = A + (size_t)m0 * lda + (i << 6);
        const __half* Bg = B + (size_t)n0 * ldb + (i << 6);
        const uint32_t da = s0 + buf * 32768;
        const uint32_t db = da + 16384;
#pragma unroll
        for (int t = 0; t < 4; t++) {
            int ch = tid + t * 256;               // 0..1023
            int r = ch >> 3;                      // row 0..127
            int s = ch & 7;                       // 16B seg 0..7
            uint32_t sw = (uint32_t)(r * 128 + ((s ^ (r & 7)) << 4));
            cp16(da + sw, Ag + (size_t)r * lda + s * 8);
            cp16(db + sw, Bg + (size_t)r * ldb + s * 8);
        }
        asm volatile("cp.async.commit_group;");
    };

    load_tile(0, 0);
    if (ntiles > 1) load_tile(1, 1); else asm volatile("cp.async.commit_group;");

    for (int i = 0; i < ntiles; i++) {
        asm volatile("cp.async.wait_group 1;");
        __syncthreads();
        if (i + 2 < ntiles) load_tile(i + 2, (i + 2) % 3);
        else asm volatile("cp.async.commit_group;");

        const uint32_t ab = s0 + (i % 3) * 32768;
        const uint32_t bb = ab + 16384;
#pragma unroll
        for (int kc = 0; kc < 4; kc++) {
            const uint32_t ax = (uint32_t)(((kc * 2 + sega) ^ a_swrow) << 4);
            const uint32_t bx = (uint32_t)(((kc * 2 + segb) ^ b_swrow) << 4);
            uint32_t a[4][4], b[2][4];
#pragma unroll
            for (int mt = 0; mt < 4; mt++) ldsm_x4(a[mt], ab + a_off[mt] + ax);
#pragma unroll
            for (int p = 0; p < 2; p++) ldsm_x4(b[p], bb + b_off[p] + bx);
#pragma unroll
            for (int mt = 0; mt < 4; mt++) {
                mma16816(c[mt][0], a[mt], b[0][0], b[0][1]);
                mma16816(c[mt][1], a[mt], b[0][2], b[0][3]);
                mma16816(c[mt][2], a[mt], b[1][0], b[1][1]);
                mma16816(c[mt][3], a[mt], b[1][2], b[1][3]);
            }
        }
    }

    // epilogue
#pragma unroll
    for (int mt = 0; mt < 4; mt++)
#pragma unroll
        for (int nt = 0; nt < 4; nt++) {
            int row = m0 + wm + mt * 16 + g;
            int col = n0 + wn + nt * 8 + t4 * 2;
            *(float2*)&C[(size_t)row * ldc + col] = make_float2(c[mt][nt][0], c[mt][nt][1]);
            *(float2*)&C[(size_t)(row + 8) * ldc + col] = make_float2(c[mt][nt][2], c[mt][nt][3]);
        }
}

// ---------------- activation split (A-side: hi,lo) ----------------
__global__ __launch_bounds__(256) void split_act(
    const float* __restrict__ X, __half* __restrict__ X2, int total)
{
    int i = blockIdx.x * 256 + threadIdx.x;
    if (i >= total) return;
    __half hi, lo;
    h_split(X[i], hi, lo);
    __half* o = X2 + 2 * (size_t)i;
    o[0] = hi; o[1] = lo;
}

// ---------------- weight transpose+round: W[K,N] -> W2t[N][2K] (B-side: hi,hi) ----------------
__global__ __launch_bounds__(1024) void transpose_split_w(
    const float* __restrict__ W, __half* __restrict__ W2t, int K, int N)
{
    __shared__ float t[32][33];
    const int kb = blockIdx.x * 32, nb = blockIdx.y * 32;
    const int tx = threadIdx.x & 31, ty = threadIdx.x >> 5;
    t[ty][tx] = W[(size_t)(kb + ty) * N + nb + tx];
    __syncthreads();
    __half hi = __float2half_rn(t[tx][ty]);
    __half* o = W2t + (size_t)(nb + ty) * (2 * K) + 2 * (kb + tx);
    o[0] = hi; o[1] = hi;
}

// ---------------- RMSNorm + split (A-side) ----------------
__global__ __launch_bounds__(256) void rmsnorm_split(
    const float* __restrict__ src, const float* __restrict__ gamma,
    __half* __restrict__ dst2, int stride, int len)
{
    const int row = blockIdx.x;
    const float* x = src + (size_t)row * stride;
    float ss = 0.f;
    for (int i = threadIdx.x; i < len; i += 256) { float v = x[i]; ss += v * v; }
#pragma unroll
    for (int o = 16; o; o >>= 1) ss += __shfl_xor_sync(0xffffffffu, ss, o);
    __shared__ float ws[8]; __shared__ float s_inv;
    if ((threadIdx.x & 31) == 0) ws[threadIdx.x >> 5] = ss;
    __syncthreads();
    if (threadIdx.x == 0) {
        float t = 0.f;
#pragma unroll
        for (int i = 0; i < 8; i++) t += ws[i];
        s_inv = rsqrtf(t / (float)len + 1e-6f);
    }
    __syncthreads();
    const float inv = s_inv;
    __half* out = dst2 + (size_t)row * 2 * len;
    for (int i = threadIdx.x; i < len; i += 256) {
        __half hi, lo;
        h_split(x[i] * gamma[i] * inv, hi, lo);
        out[2 * i] = hi; out[2 * i + 1] = lo;
    }
}

// ---------------- RoPE + pack + split ----------------
__global__ __launch_bounds__(192) void rope_pack_split(
    const float* __restrict__ qp, const float* __restrict__ kvp,
    const float* __restrict__ fused,
    __half* __restrict__ Q2, __half* __restrict__ K2,
    __half* __restrict__ V2)
{
    const int s = blockIdx.x, h = blockIdx.y, d = threadIdx.x;
    const float scale = 0.07216878364870323f; // 1/sqrt(192)
    float qv, kv;
    if (d < DN) {
        qv = qp[(size_t)s * QB_N + h * DFULL + d] * scale;
        kv = kvp[(size_t)s * KVB_N + h * (DN + DV) + d];
        float vv = kvp[(size_t)s * KVB_N + h * (DN + DV) + DN + d];
        __half vhi = __float2half_rn(vv);
        __half* vp = V2 + ((size_t)h * DV + d) * K2_SEQ + 2 * s;
        vp[0] = vhi; vp[1] = vhi;             // B-side (hi,hi)
    } else {
        int j = d - DN, i = j & 31;
        float inv_freq = powf(10000.f, -(float)(2 * i) / 64.f);
        float sn, cs;
        sincosf((float)s * inv_freq, &sn, &cs);
        size_t qoff = (size_t)s * QB_N + h * DFULL + DN;
        float qpe = qp[qoff + j];
        float qrot = (j < 32) ? -qp[qoff + j + 32] : qp[qoff + j - 32];
        size_t koff = (size_t)s * FUSED_NPAD + (QL + KL);
        float kpe = fused[koff + j];
        float krot = (j < 32) ? -fused[koff + j + 32] : fused[koff + j - 32];
        qv = (qpe * cs + qrot * sn) * scale;
        kv = kpe * cs + krot * sn;
    }
    __half qhi, qlo;
    h_split(qv, qhi, qlo);
    __half khi = __float2half_rn(kv);
    __half* qo = Q2 + ((size_t)h * SEQ + s) * K2_D + 2 * d;
    qo[0] = qhi; qo[1] = qlo;                 // A-side (hi,lo)
    __half* ko = K2 + ((size_t)h * SEQ + s) * K2_D + 2 * d;
    ko[0] = khi; ko[1] = khi;                 // B-side (hi,hi)
}

// ---------------- causal softmax + split (A-side); tail stays zero ----------------
__global__ __launch_bounds__(256) void softmax_split(
    const float* __restrict__ Sc, __half* __restrict__ P2)
{
    const int q = blockIdx.x, h = blockIdx.y, tid = threadIdx.x;
    const float* row = Sc + ((size_t)h * SEQ + q) * SEQ;
    __half* out = P2 + ((size_t)h * SEQ + q) * K2_SEQ;
    const int n = q + 1;
    __shared__ float red[8]; __shared__ float bc;

    float mx = -INFINITY;
    for (int i = tid; i < n; i += 256) mx = fmaxf(mx, row[i]);
#pragma unroll
    for (int o = 16; o; o >>= 1) mx = fmaxf(mx, __shfl_xor_sync(0xffffffffu, mx, o));
    if ((tid & 31) == 0) red[tid >> 5] = mx;
    __syncthreads();
    if (tid == 0) {
        float m = red[0];
#pragma unroll
        for (int i = 1; i < 8; i++) m = fmaxf(m, red[i]);
        bc = m;
    }
    __syncthreads();
    const float M = bc;
    float sm = 0.f;
    for (int i = tid; i < n; i += 256) sm += __expf(row[i] - M);
#pragma unroll
    for (int o = 16; o; o >>= 1) sm += __shfl_xor_sync(0xffffffffu, sm, o);
    if ((tid & 31) == 0) red[tid >> 5] = sm;
    __syncthreads();
    if (tid == 0) {
        float t = 0.f;
#pragma unroll
        for (int i = 0; i < 8; i++) t += red[i];
        bc = 1.f / t;
    }
    __syncthreads();
    const float inv = bc;
    for (int i = tid; i < n; i += 256) {
        __half hi, lo;
        h_split(__expf(row[i] - M) * inv, hi, lo);
        out[2 * i] = hi; out[2 * i + 1] = lo;
    }
}

// ---------------- launcher ----------------
extern "C" void kernel_launch(void* const* d_in, const int* in_sizes, int n_in,
                              void* d_out, int out_size)
{
    const float* hidden     = (const float*)d_in[0];
    const float* w_kv_a     = (const float*)d_in[1];
    const float* q_a_gamma  = (const float*)d_in[2];
    const float* w_qb       = (const float*)d_in[3];
    const float* kv_a_gamma = (const float*)d_in[4];
    const float* w_kvb      = (const float*)d_in[5];
    const float* w_o        = (const float*)d_in[6];
    float* out = (float*)d_out;

    static float *fused = nullptr, *qp, *kvp, *Sc, *attn;
    static __half *H2, *QN2, *KVN2, *ATTN2, *WKVA2, *WQB2, *WKVB2, *WO2, *Q2, *K2, *V2, *P2;
    if (!fused) {
        cudaGetSymbolAddress((void**)&fused, g_fused);
        cudaGetSymbolAddress((void**)&qp,    g_qp);
        cudaGetSymbolAddress((void**)&kvp,   g_kvp);
        cudaGetSymbolAddress((void**)&Sc,    g_Sc);
        cudaGetSymbolAddress((void**)&attn,  g_attn);
        cudaGetSymbolAddress((void**)&H2,    g_H3);
        cudaGetSymbolAddress((void**)&QN2,   g_QN3);
        cudaGetSymbolAddress((void**)&KVN2,  g_KVN3);
        cudaGetSymbolAddress((void**)&ATTN2, g_ATTN3);
        cudaGetSymbolAddress((void**)&WKVA2, g_WKVA3);
        cudaGetSymbolAddress((void**)&WQB2,  g_WQB3);
        cudaGetSymbolAddress((void**)&WKVB2, g_WKVB3);
        cudaGetSymbolAddress((void**)&WO2,   g_WO3);
        cudaGetSymbolAddress((void**)&Q2,    g_Q3);
        cudaGetSymbolAddress((void**)&K2,    g_K3);
        cudaGetSymbolAddress((void**)&V2,    g_V3);
        cudaGetSymbolAddress((void**)&P2,    g_P3);
        cudaFuncSetAttribute(gemm_fp16, cudaFuncAttributeMaxDynamicSharedMemorySize, GSMEM);
    }

    // operand preparation
    split_act<<<(SEQ * HDIM + 255) / 256, 256>>>(hidden, H2, SEQ * HDIM);
    transpose_split_w<<<dim3(HDIM / 32, FUSED_REAL / 32), 1024>>>(w_kv_a, WKVA2, HDIM, FUSED_REAL);
    transpose_split_w<<<dim3(QL / 32, QB_N / 32), 1024>>>(w_qb, WQB2, QL, QB_N);
    transpose_split_w<<<dim3(KL / 32, KVB_N / 32), 1024>>>(w_kvb, WKVB2, KL, KVB_N);
    transpose_split_w<<<dim3(HDIM / 32, HDIM / 32), 1024>>>(w_o, WO2, HDIM, HDIM);

    // 1) fused = hidden @ w_kv_a
    gemm_fp16<<<dim3(FUSED_NPAD / 128, SEQ / 128), 256, GSMEM>>>(
        H2, 0, WKVA2, 0, fused, 0, K2_H, K2_H, FUSED_NPAD, K2_H, 0);

    // 2) rmsnorm + split
    rmsnorm_split<<<SEQ, 256>>>(fused, q_a_gamma, QN2, FUSED_NPAD, QL);
    rmsnorm_split<<<SEQ, 256>>>(fused + QL, kv_a_gamma, KVN2, FUSED_NPAD, KL);

    // 3) projections
    gemm_fp16<<<dim3(QB_N / 128, SEQ / 128), 256, GSMEM>>>(
        QN2, 0, WQB2, 0, qp, 0, K2_QL, K2_QL, QB_N, K2_QL, 0);
    gemm_fp16<<<dim3(KVB_N / 128, SEQ / 128), 256, GSMEM>>>(
        KVN2, 0, WKVB2, 0, kvp, 0, K2_KL, K2_KL, KVB_N, K2_KL, 0);

    // 4) rope + pack + split
    rope_pack_split<<<dim3(SEQ, NH), 192>>>(qp, kvp, fused, Q2, K2, V2);

    // 5) scores = Q @ K^T (causal block-skip), per head
    gemm_fp16<<<dim3(SEQ / 128, SEQ / 128, NH), 256, GSMEM>>>(
        Q2, (long long)SEQ * K2_D, K2, (long long)SEQ * K2_D,
        Sc, (long long)SEQ * SEQ, K2_D, K2_D, SEQ, K2_D, 1);

    // 6) softmax + split
    softmax_split<<<dim3(SEQ, NH), 256>>>(Sc, P2);

    // 7) attn = P @ V (causal k-limit), per head
    gemm_fp16<<<dim3(1, SEQ / 128, NH), 256, GSMEM>>>(
        P2, (long long)SEQ * K2_SEQ, V2, (long long)DV * K2_SEQ,
        attn, (long long)DV, K2_SEQ, K2_SEQ, NH * DV, K2_SEQ, 2);

    // 8) out = attn @ w_o
    split_act<<<(SEQ * HDIM + 255) / 256, 256>>>(attn, ATTN2, SEQ * HDIM);
    gemm_fp16<<<dim3(HDIM / 128, SEQ / 128), 256, GSMEM>>>(
        ATTN2, 0, WO2, 0, out, 0, K2_H, K2_H, HDIM, K2_H, 0);
}

// round 10
// speedup vs baseline: 2.4029x; 1.5614x over previous
#include <cuda_runtime.h>
#include <cuda_fp16.h>
#include <math.h>
#include <stdint.h>

#define SEQ    2048
#define HDIM   2048
#define NH     16
#define DN     128
#define DR     64
#define DV     128
#define QL     1536
#define KL     512
#define DFULL  192
#define FUSED_NPAD 2176
#define FUSED_REAL 2112
#define QB_N   3072
#define KVB_N  4096

// ---------------- device scratch (zero-initialized) ----------------
__device__ float g_fused[SEQ * FUSED_NPAD];
__device__ float g_qp[SEQ * QB_N];
__device__ float g_kvp[SEQ * KVB_N];
__device__ float g_Sc[NH * SEQ * SEQ];
__device__ float g_attn[SEQ * HDIM];
__device__ __half g_H2   [SEQ * HDIM];
__device__ __half g_QN2  [SEQ * QL];
__device__ __half g_KVN2 [SEQ * KL];
__device__ __half g_ATTN2[SEQ * HDIM];
__device__ __half g_WKVA2[FUSED_NPAD * HDIM];   // rows >= 2112 stay 0
__device__ __half g_WQB2 [QB_N * QL];
__device__ __half g_WKVB2[KVB_N * KL];
__device__ __half g_WO2  [HDIM * HDIM];
__device__ __half g_Q2 [NH * SEQ * DFULL];
__device__ __half g_K2 [NH * SEQ * DFULL];
__device__ __half g_V2 [NH * DV * SEQ];         // [h][d][s]
__device__ __half g_P2 [NH * SEQ * SEQ];        // tail (k>q) stays 0

// ---------------- helpers ----------------
__device__ __forceinline__ uint32_t smem_u32(const void* p) {
    uint32_t a;
    asm("{ .reg .u64 t; cvta.to.shared.u64 t, %1; cvt.u32.u64 %0, t; }" : "=r"(a) : "l"(p));
    return a;
}
__device__ __forceinline__ void cp16(uint32_t dst, const void* src) {
    asm volatile("cp.async.cg.shared.global [%0], [%1], 16;" :: "r"(dst), "l"(src));
}
__device__ __forceinline__ void ldsm_x4(uint32_t* r, uint32_t a) {
    asm volatile("ldmatrix.sync.aligned.m8n8.x4.shared.b16 {%0,%1,%2,%3}, [%4];"
                 : "=r"(r[0]), "=r"(r[1]), "=r"(r[2]), "=r"(r[3]) : "r"(a));
}
__device__ __forceinline__ void mma16816(float* c, const uint32_t* a, uint32_t b0, uint32_t b1) {
    asm volatile(
        "mma.sync.aligned.m16n8k16.row.col.f32.f16.f16.f32 "
        "{%0,%1,%2,%3}, {%4,%5,%6,%7}, {%8,%9}, {%0,%1,%2,%3};"
        : "+f"(c[0]), "+f"(c[1]), "+f"(c[2]), "+f"(c[3])
        : "r"(a[0]), "r"(a[1]), "r"(a[2]), "r"(a[3]), "r"(b0), "r"(b1));
}

// ============================================================================
// fp16 GEMM: C[m,n] = sum_k A[m,k] B[n,k] (both K-major fp16, C fp32)
// Tile 128x128, BK=64, 256 threads (8 warps, warp tile 64x32),
// 3-stage cp.async pipeline (single barrier per chunk), ldmatrix.x4.
// mode 0: plain; 1: skip n0 > m0+127; 2: k-tiles limited to (m0+128)/64.
// ============================================================================
#define GSMEM (3 * 32768)

__global__ __launch_bounds__(256) void gemm_fp16(
    const __half* __restrict__ A, long long sA,
    const __half* __restrict__ B, long long sB,
    float* __restrict__ C, long long sC,
    int lda, int ldb, int ldc, int K, int mode)
{
    const int n0 = blockIdx.x * 128;
    const int m0 = blockIdx.y * 128;
    if (mode == 1 && n0 > m0 + 127) return;
    A += (size_t)blockIdx.z * sA;
    B += (size_t)blockIdx.z * sB;
    C += (size_t)blockIdx.z * sC;

    int ntiles = K >> 6;
    if (mode == 2) {
        int lim = (m0 + 128) >> 6;
        if (lim < ntiles) ntiles = lim;
    }

    extern __shared__ char smraw[];
    const uint32_t s0 = smem_u32(smraw);   // stage s: A at s*32768, B at +16384

    const int tid = threadIdx.x;
    const int lane = tid & 31;
    const int wid = tid >> 5;
    const int wm = (wid & 1) * 64;
    const int wn = (wid >> 1) * 32;
    const int g = lane >> 2, t4 = lane & 3;

    // A ldmatrix addressing (x4: 16 rows x 2 k-segs)
    const int ra = lane & 15;
    const int sega = (lane >> 4) & 1;
    // B ldmatrix addressing (x4 covers 2 n-slabs x 2 k-segs)
    const int rb = (lane >> 4) * 8 + (lane & 7);
    const int segb = (lane >> 3) & 1;
    uint32_t a_off[4], b_off[2];
#pragma unroll
    for (int mt = 0; mt < 4; mt++) a_off[mt] = (uint32_t)((wm + mt * 16 + ra) * 128);
#pragma unroll
    for (int p = 0; p < 2; p++) b_off[p] = (uint32_t)((wn + p * 16 + rb) * 128);
    const int a_swrow = ra & 7;
    const int b_swrow = rb & 7;

    float c[4][4][4];
#pragma unroll
    for (int i = 0; i < 4; i++)
#pragma unroll
        for (int j = 0; j < 4; j++)
#pragma unroll
            for (int e = 0; e < 4; e++) c[i][j][e] = 0.f;

    auto load_tile = [&](int i, int buf) {
        const __half* Ag = A + (size_t)m0 * lda + (i << 6);
        const __half* Bg = B + (size_t)n0 * ldb + (i << 6);
        const uint32_t da = s0 + buf * 32768;
        const uint32_t db = da + 16384;
#pragma unroll
        for (int t = 0; t < 4; t++) {
            int ch = tid + t * 256;               // 0..1023
            int r = ch >> 3;                      // row 0..127
            int s = ch & 7;                       // 16B seg 0..7
            uint32_t sw = (uint32_t)(r * 128 + ((s ^ (r & 7)) << 4));
            cp16(da + sw, Ag + (size_t)r * lda + s * 8);
            cp16(db + sw, Bg + (size_t)r * ldb + s * 8);
        }
        asm volatile("cp.async.commit_group;");
    };

    load_tile(0, 0);
    if (ntiles > 1) load_tile(1, 1); else asm volatile("cp.async.commit_group;");

    for (int i = 0; i < ntiles; i++) {
        asm volatile("cp.async.wait_group 1;");
        __syncthreads();
        if (i + 2 < ntiles) load_tile(i + 2, (i + 2) % 3);
        else asm volatile("cp.async.commit_group;");

        const uint32_t ab = s0 + (i % 3) * 32768;
        const uint32_t bb = ab + 16384;
#pragma unroll
        for (int kc = 0; kc < 4; kc++) {
            const uint32_t ax = (uint32_t)(((kc * 2 + sega) ^ a_swrow) << 4);
            const uint32_t bx = (uint32_t)(((kc * 2 + segb) ^ b_swrow) << 4);
            uint32_t a[4][4], b[2][4];
#pragma unroll
            for (int mt = 0; mt < 4; mt++) ldsm_x4(a[mt], ab + a_off[mt] + ax);
#pragma unroll
            for (int p = 0; p < 2; p++) ldsm_x4(b[p], bb + b_off[p] + bx);
#pragma unroll
            for (int mt = 0; mt < 4; mt++) {
                mma16816(c[mt][0], a[mt], b[0][0], b[0][1]);
                mma16816(c[mt][1], a[mt], b[0][2], b[0][3]);
                mma16816(c[mt][2], a[mt], b[1][0], b[1][1]);
                mma16816(c[mt][3], a[mt], b[1][2], b[1][3]);
            }
        }
    }

    // epilogue
#pragma unroll
    for (int mt = 0; mt < 4; mt++)
#pragma unroll
        for (int nt = 0; nt < 4; nt++) {
            int row = m0 + wm + mt * 16 + g;
            int col = n0 + wn + nt * 8 + t4 * 2;
            *(float2*)&C[(size_t)row * ldc + col] = make_float2(c[mt][nt][0], c[mt][nt][1]);
            *(float2*)&C[(size_t)(row + 8) * ldc + col] = make_float2(c[mt][nt][2], c[mt][nt][3]);
        }
}

// ---------------- fp32 -> fp16 convert ----------------
__global__ __launch_bounds__(256) void cvt_act(
    const float* __restrict__ X, __half* __restrict__ X2, int total)
{
    int i = blockIdx.x * 256 + threadIdx.x;
    if (i >= total) return;
    X2[i] = __float2half_rn(X[i]);
}

// ---------------- weight transpose+convert: W[K,N] -> Wt[N,K] fp16 ----------------
__global__ __launch_bounds__(1024) void transpose_w_h(
    const float* __restrict__ W, __half* __restrict__ Wt, int K, int N)
{
    __shared__ float t[32][33];
    const int kb = blockIdx.x * 32, nb = blockIdx.y * 32;
    const int tx = threadIdx.x & 31, ty = threadIdx.x >> 5;
    t[ty][tx] = W[(size_t)(kb + ty) * N + nb + tx];
    __syncthreads();
    Wt[(size_t)(nb + ty) * K + kb + tx] = __float2half_rn(t[tx][ty]);
}

// ---------------- RMSNorm -> fp16 ----------------
__global__ __launch_bounds__(256) void rmsnorm_h(
    const float* __restrict__ src, const float* __restrict__ gamma,
    __half* __restrict__ dst, int stride, int len)
{
    const int row = blockIdx.x;
    const float* x = src + (size_t)row * stride;
    float ss = 0.f;
    for (int i = threadIdx.x; i < len; i += 256) { float v = x[i]; ss += v * v; }
#pragma unroll
    for (int o = 16; o; o >>= 1) ss += __shfl_xor_sync(0xffffffffu, ss, o);
    __shared__ float ws[8]; __shared__ float s_inv;
    if ((threadIdx.x & 31) == 0) ws[threadIdx.x >> 5] = ss;
    __syncthreads();
    if (threadIdx.x == 0) {
        float t = 0.f;
#pragma unroll
        for (int i = 0; i < 8; i++) t += ws[i];
        s_inv = rsqrtf(t / (float)len + 1e-6f);
    }
    __syncthreads();
    const float inv = s_inv;
    __half* out = dst + (size_t)row * len;
    for (int i = threadIdx.x; i < len; i += 256)
        out[i] = __float2half_rn(x[i] * gamma[i] * inv);
}

// ---------------- RoPE + pack -> fp16 ----------------
__global__ __launch_bounds__(192) void rope_pack_h(
    const float* __restrict__ qp, const float* __restrict__ kvp,
    const float* __restrict__ fused,
    __half* __restrict__ Q2, __half* __restrict__ K2,
    __half* __restrict__ V2)
{
    const int s = blockIdx.x, h = blockIdx.y, d = threadIdx.x;
    const float scale = 0.07216878364870323f; // 1/sqrt(192)
    float qv, kv;
    if (d < DN) {
        qv = qp[(size_t)s * QB_N + h * DFULL + d] * scale;
        kv = kvp[(size_t)s * KVB_N + h * (DN + DV) + d];
        float vv = kvp[(size_t)s * KVB_N + h * (DN + DV) + DN + d];
        V2[((size_t)h * DV + d) * SEQ + s] = __float2half_rn(vv);
    } else {
        int j = d - DN, i = j & 31;
        float inv_freq = powf(10000.f, -(float)(2 * i) / 64.f);
        float sn, cs;
        sincosf((float)s * inv_freq, &sn, &cs);
        size_t qoff = (size_t)s * QB_N + h * DFULL + DN;
        float qpe = qp[qoff + j];
        float qrot = (j < 32) ? -qp[qoff + j + 32] : qp[qoff + j - 32];
        size_t koff = (size_t)s * FUSED_NPAD + (QL + KL);
        float kpe = fused[koff + j];
        float krot = (j < 32) ? -fused[koff + j + 32] : fused[koff + j - 32];
        qv = (qpe * cs + qrot * sn) * scale;
        kv = kpe * cs + krot * sn;
    }
    Q2[((size_t)h * SEQ + s) * DFULL + d] = __float2half_rn(qv);
    K2[((size_t)h * SEQ + s) * DFULL + d] = __float2half_rn(kv);
}

// ---------------- causal softmax -> fp16 P; tail stays zero ----------------
__global__ __launch_bounds__(256) void softmax_h(
    const float* __restrict__ Sc, __half* __restrict__ P2)
{
    const int q = blockIdx.x, h = blockIdx.y, tid = threadIdx.x;
    const float* row = Sc + ((size_t)h * SEQ + q) * SEQ;
    __half* out = P2 + ((size_t)h * SEQ + q) * SEQ;
    const int n = q + 1;
    __shared__ float red[8]; __shared__ float bc;

    float mx = -INFINITY;
    for (int i = tid; i < n; i += 256) mx = fmaxf(mx, row[i]);
#pragma unroll
    for (int o = 16; o; o >>= 1) mx = fmaxf(mx, __shfl_xor_sync(0xffffffffu, mx, o));
    if ((tid & 31) == 0) red[tid >> 5] = mx;
    __syncthreads();
    if (tid == 0) {
        float m = red[0];
#pragma unroll
        for (int i = 1; i < 8; i++) m = fmaxf(m, red[i]);
        bc = m;
    }
    __syncthreads();
    const float M = bc;
    float sm = 0.f;
    for (int i = tid; i < n; i += 256) sm += __expf(row[i] - M);
#pragma unroll
    for (int o = 16; o; o >>= 1) sm += __shfl_xor_sync(0xffffffffu, sm, o);
    if ((tid & 31) == 0) red[tid >> 5] = sm;
    __syncthreads();
    if (tid == 0) {
        float t = 0.f;
#pragma unroll
        for (int i = 0; i < 8; i++) t += red[i];
        bc = 1.f / t;
    }
    __syncthreads();
    const float inv = bc;
    for (int i = tid; i < n; i += 256)
        out[i] = __float2half_rn(__expf(row[i] - M) * inv);
}

// ---------------- launcher ----------------
extern "C" void kernel_launch(void* const* d_in, const int* in_sizes, int n_in,
                              void* d_out, int out_size)
{
    const float* hidden     = (const float*)d_in[0];
    const float* w_kv_a     = (const float*)d_in[1];
    const float* q_a_gamma  = (const float*)d_in[2];
    const float* w_qb       = (const float*)d_in[3];
    const float* kv_a_gamma = (const float*)d_in[4];
    const float* w_kvb      = (const float*)d_in[5];
    const float* w_o        = (const float*)d_in[6];
    float* out = (float*)d_out;

    static float *fused = nullptr, *qp, *kvp, *Sc, *attn;
    static __half *H2, *QN2, *KVN2, *ATTN2, *WKVA2, *WQB2, *WKVB2, *WO2, *Q2, *K2, *V2, *P2;
    if (!fused) {
        cudaGetSymbolAddress((void**)&fused, g_fused);
        cudaGetSymbolAddress((void**)&qp,    g_qp);
        cudaGetSymbolAddress((void**)&kvp,   g_kvp);
        cudaGetSymbolAddress((void**)&Sc,    g_Sc);
        cudaGetSymbolAddress((void**)&attn,  g_attn);
        cudaGetSymbolAddress((void**)&H2,    g_H2);
        cudaGetSymbolAddress((void**)&QN2,   g_QN2);
        cudaGetSymbolAddress((void**)&KVN2,  g_KVN2);
        cudaGetSymbolAddress((void**)&ATTN2, g_ATTN2);
        cudaGetSymbolAddress((void**)&WKVA2, g_WKVA2);
        cudaGetSymbolAddress((void**)&WQB2,  g_WQB2);
        cudaGetSymbolAddress((void**)&WKVB2, g_WKVB2);
        cudaGetSymbolAddress((void**)&WO2,   g_WO2);
        cudaGetSymbolAddress((void**)&Q2,    g_Q2);
        cudaGetSymbolAddress((void**)&K2,    g_K2);
        cudaGetSymbolAddress((void**)&V2,    g_V2);
        cudaGetSymbolAddress((void**)&P2,    g_P2);
        cudaFuncSetAttribute(gemm_fp16, cudaFuncAttributeMaxDynamicSharedMemorySize, GSMEM);
    }

    // operand preparation
    cvt_act<<<(SEQ * HDIM + 255) / 256, 256>>>(hidden, H2, SEQ * HDIM);
    transpose_w_h<<<dim3(HDIM / 32, FUSED_REAL / 32), 1024>>>(w_kv_a, WKVA2, HDIM, FUSED_REAL);
    transpose_w_h<<<dim3(QL / 32, QB_N / 32), 1024>>>(w_qb, WQB2, QL, QB_N);
    transpose_w_h<<<dim3(KL / 32, KVB_N / 32), 1024>>>(w_kvb, WKVB2, KL, KVB_N);
    transpose_w_h<<<dim3(HDIM / 32, HDIM / 32), 1024>>>(w_o, WO2, HDIM, HDIM);

    // 1) fused = hidden @ w_kv_a
    gemm_fp16<<<dim3(FUSED_NPAD / 128, SEQ / 128), 256, GSMEM>>>(
        H2, 0, WKVA2, 0, fused, 0, HDIM, HDIM, FUSED_NPAD, HDIM, 0);

    // 2) rmsnorm -> fp16
    rmsnorm_h<<<SEQ, 256>>>(fused, q_a_gamma, QN2, FUSED_NPAD, QL);
    rmsnorm_h<<<SEQ, 256>>>(fused + QL, kv_a_gamma, KVN2, FUSED_NPAD, KL);

    // 3) projections
    gemm_fp16<<<dim3(QB_N / 128, SEQ / 128), 256, GSMEM>>>(
        QN2, 0, WQB2, 0, qp, 0, QL, QL, QB_N, QL, 0);
    gemm_fp16<<<dim3(KVB_N / 128, SEQ / 128), 256, GSMEM>>>(
        KVN2, 0, WKVB2, 0, kvp, 0, KL, KL, KVB_N, KL, 0);

    // 4) rope + pack -> fp16
    rope_pack_h<<<dim3(SEQ, NH), 192>>>(qp, kvp, fused, Q2, K2, V2);

    // 5) scores = Q @ K^T (causal block-skip), per head
    gemm_fp16<<<dim3(SEQ / 128, SEQ / 128, NH), 256, GSMEM>>>(
        Q2, (long long)SEQ * DFULL, K2, (long long)SEQ * DFULL,
        Sc, (long long)SEQ * SEQ, DFULL, DFULL, SEQ, DFULL, 1);

    // 6) softmax -> fp16 P
    softmax_h<<<dim3(SEQ, NH), 256>>>(Sc, P2);

    // 7) attn = P @ V (causal k-limit), per head
    gemm_fp16<<<dim3(1, SEQ / 128, NH), 256, GSMEM>>>(
        P2, (long long)SEQ * SEQ, V2, (long long)DV * SEQ,
        attn, (long long)DV, SEQ, SEQ, NH * DV, SEQ, 2);

    // 8) out = attn @ w_o
    cvt_act<<<(SEQ * HDIM + 255) / 256, 256>>>(attn, ATTN2, SEQ * HDIM);
    gemm_fp16<<<dim3(HDIM / 128, SEQ / 128), 256, GSMEM>>>(
        ATTN2, 0, WO2, 0, out, 0, HDIM, HDIM, HDIM, HDIM, 0);
}

// round 11
// speedup vs baseline: 2.9011x; 1.2073x over previous
#include <cuda_runtime.h>
#include <cuda_fp16.h>
#include <math.h>
#include <stdint.h>

#define SEQ    2048
#define HDIM   2048
#define NH     16
#define DN     128
#define DR     64
#define DV     128
#define QL     1536
#define KL     512
#define DFULL  192
#define FUSED_NPAD 2176
#define FUSED_REAL 2112
#define QB_N   3072
#define KVB_N  4096

// ---------------- device scratch (zero-initialized) ----------------
__device__ float g_fused[SEQ * FUSED_NPAD];
__device__ float g_qp[SEQ * QB_N];
__device__ float g_kvp[SEQ * KVB_N];
__device__ __half g_H2   [SEQ * HDIM];
__device__ __half g_QN2  [SEQ * QL];
__device__ __half g_KVN2 [SEQ * KL];
__device__ __half g_ATTN2[SEQ * HDIM];
__device__ __half g_WKVA2[FUSED_NPAD * HDIM];   // rows >= 2112 stay 0
__device__ __half g_WQB2 [QB_N * QL];
__device__ __half g_WKVB2[KVB_N * KL];
__device__ __half g_WO2  [HDIM * HDIM];
__device__ __half g_Q2 [NH * SEQ * DFULL];
__device__ __half g_K2 [NH * SEQ * DFULL];
__device__ __half g_V2 [NH * DV * SEQ];         // [h][d][s]

// ---------------- helpers ----------------
__device__ __forceinline__ uint32_t smem_u32(const void* p) {
    uint32_t a;
    asm("{ .reg .u64 t; cvta.to.shared.u64 t, %1; cvt.u32.u64 %0, t; }" : "=r"(a) : "l"(p));
    return a;
}
__device__ __forceinline__ void cp16(uint32_t dst, const void* src) {
    asm volatile("cp.async.cg.shared.global [%0], [%1], 16;" :: "r"(dst), "l"(src));
}
__device__ __forceinline__ void ldsm_x4(uint32_t* r, uint32_t a) {
    asm volatile("ldmatrix.sync.aligned.m8n8.x4.shared.b16 {%0,%1,%2,%3}, [%4];"
                 : "=r"(r[0]), "=r"(r[1]), "=r"(r[2]), "=r"(r[3]) : "r"(a));
}
__device__ __forceinline__ void mma16816(float* c, const uint32_t* a, uint32_t b0, uint32_t b1) {
    asm volatile(
        "mma.sync.aligned.m16n8k16.row.col.f32.f16.f16.f32 "
        "{%0,%1,%2,%3}, {%4,%5,%6,%7}, {%8,%9}, {%0,%1,%2,%3};"
        : "+f"(c[0]), "+f"(c[1]), "+f"(c[2]), "+f"(c[3])
        : "r"(a[0]), "r"(a[1]), "r"(a[2]), "r"(a[3]), "r"(b0), "r"(b1));
}

// ============================================================================
// fp16 GEMM (unchanged from R10 best): C = A B^T, K-major fp16 operands.
// ============================================================================
#define GSMEM (3 * 32768)

__global__ __launch_bounds__(256) void gemm_fp16(
    const __half* __restrict__ A, long long sA,
    const __half* __restrict__ B, long long sB,
    float* __restrict__ C, long long sC,
    int lda, int ldb, int ldc, int K, int mode)
{
    const int n0 = blockIdx.x * 128;
    const int m0 = blockIdx.y * 128;
    if (mode == 1 && n0 > m0 + 127) return;
    A += (size_t)blockIdx.z * sA;
    B += (size_t)blockIdx.z * sB;
    C += (size_t)blockIdx.z * sC;

    int ntiles = K >> 6;
    if (mode == 2) {
        int lim = (m0 + 128) >> 6;
        if (lim < ntiles) ntiles = lim;
    }

    extern __shared__ char smraw[];
    const uint32_t s0 = smem_u32(smraw);

    const int tid = threadIdx.x;
    const int lane = tid & 31;
    const int wid = tid >> 5;
    const int wm = (wid & 1) * 64;
    const int wn = (wid >> 1) * 32;
    const int g = lane >> 2, t4 = lane & 3;

    const int ra = lane & 15;
    const int sega = (lane >> 4) & 1;
    const int rb = (lane >> 4) * 8 + (lane & 7);
    const int segb = (lane >> 3) & 1;
    uint32_t a_off[4], b_off[2];
#pragma unroll
    for (int mt = 0; mt < 4; mt++) a_off[mt] = (uint32_t)((wm + mt * 16 + ra) * 128);
#pragma unroll
    for (int p = 0; p < 2; p++) b_off[p] = (uint32_t)((wn + p * 16 + rb) * 128);
    const int a_swrow = ra & 7;
    const int b_swrow = rb & 7;

    float c[4][4][4];
#pragma unroll
    for (int i = 0; i < 4; i++)
#pragma unroll
        for (int j = 0; j < 4; j++)
#pragma unroll
            for (int e = 0; e < 4; e++) c[i][j][e] = 0.f;

    auto load_tile = [&](int i, int buf) {
        const __half* Ag = A + (size_t)m0 * lda + (i << 6);
        const __half* Bg = B + (size_t)n0 * ldb + (i << 6);
        const uint32_t da = s0 + buf * 32768;
        const uint32_t db = da + 16384;
#pragma unroll
        for (int t = 0; t < 4; t++) {
            int ch = tid + t * 256;
            int r = ch >> 3;
            int s = ch & 7;
            uint32_t sw = (uint32_t)(r * 128 + ((s ^ (r & 7)) << 4));
            cp16(da + sw, Ag + (size_t)r * lda + s * 8);
            cp16(db + sw, Bg + (size_t)r * ldb + s * 8);
        }
        asm volatile("cp.async.commit_group;");
    };

    load_tile(0, 0);
    if (ntiles > 1) load_tile(1, 1); else asm volatile("cp.async.commit_group;");

    for (int i = 0; i < ntiles; i++) {
        asm volatile("cp.async.wait_group 1;");
        __syncthreads();
        if (i + 2 < ntiles) load_tile(i + 2, (i + 2) % 3);
        else asm volatile("cp.async.commit_group;");

        const uint32_t ab = s0 + (i % 3) * 32768;
        const uint32_t bb = ab + 16384;
#pragma unroll
        for (int kc = 0; kc < 4; kc++) {
            const uint32_t ax = (uint32_t)(((kc * 2 + sega) ^ a_swrow) << 4);
            const uint32_t bx = (uint32_t)(((kc * 2 + segb) ^ b_swrow) << 4);
            uint32_t a[4][4], b[2][4];
#pragma unroll
            for (int mt = 0; mt < 4; mt++) ldsm_x4(a[mt], ab + a_off[mt] + ax);
#pragma unroll
            for (int p = 0; p < 2; p++) ldsm_x4(b[p], bb + b_off[p] + bx);
#pragma unroll
            for (int mt = 0; mt < 4; mt++) {
                mma16816(c[mt][0], a[mt], b[0][0], b[0][1]);
                mma16816(c[mt][1], a[mt], b[0][2], b[0][3]);
                mma16816(c[mt][2], a[mt], b[1][0], b[1][1]);
                mma16816(c[mt][3], a[mt], b[1][2], b[1][3]);
            }
        }
    }

#pragma unroll
    for (int mt = 0; mt < 4; mt++)
#pragma unroll
        for (int nt = 0; nt < 4; nt++) {
            int row = m0 + wm + mt * 16 + g;
            int col = n0 + wn + nt * 8 + t4 * 2;
            *(float2*)&C[(size_t)row * ldc + col] = make_float2(c[mt][nt][0], c[mt][nt][1]);
            *(float2*)&C[(size_t)(row + 8) * ldc + col] = make_float2(c[mt][nt][2], c[mt][nt][3]);
        }
}

// ============================================================================
// Fused flash attention (causal), fp16 mma, online softmax.
// CTA: 128 q-rows x 1 head; 8 warps, each m16. K-blocks of 64, 2-stage cp.async.
// Q smem [128][192] (384B rows, 16B-seg swizzle s^(r&7)); K stage [64][192];
// V stage [128 dv][64 s] (128B rows). Output fp16 to O[s][h*128+dv].
// ============================================================================
#define FSMEM (49152 + 2 * 24576 + 2 * 16384)   // 131072

__global__ __launch_bounds__(256) void flash_mma(
    const __half* __restrict__ Qg_, const __half* __restrict__ Kg_,
    const __half* __restrict__ Vg_, __half* __restrict__ O)
{
    const int qb = (int)(gridDim.x - 1) - (int)blockIdx.x;  // big tiles first
    const int h = blockIdx.y;
    const int kend = 2 * qb + 2;

    extern __shared__ char sm[];
    const uint32_t sQ = smem_u32(sm);
    const uint32_t sK = sQ + 49152;
    const uint32_t sV = sK + 2 * 24576;

    const int tid = threadIdx.x, lane = tid & 31, w = tid >> 5;
    const int g = lane >> 2, t4 = lane & 3;

    const __half* Qg = Qg_ + ((size_t)h * SEQ + (size_t)qb * 128) * DFULL;
    const __half* Kg = Kg_ + (size_t)h * SEQ * DFULL;
    const __half* Vg = Vg_ + (size_t)h * DV * SEQ;

    // Q: 128 rows x 24 segs
    {
#pragma unroll
        for (int t = 0; t < 12; t++) {
            int ch = tid + t * 256;
            int r = ch / 24, s = ch % 24;
            uint32_t sw = (uint32_t)(r * 384 + ((s ^ (r & 7)) << 4));
            cp16(sQ + sw, Qg + r * DFULL + s * 8);
        }
        asm volatile("cp.async.commit_group;");
    }
    auto load_kv = [&](int kb, int buf) {
        const __half* Kt = Kg + (size_t)kb * 64 * DFULL;
#pragma unroll
        for (int t = 0; t < 6; t++) {
            int ch = tid + t * 256;              // 0..1535
            int r = ch / 24, s = ch % 24;
            uint32_t sw = (uint32_t)(r * 384 + ((s ^ (r & 7)) << 4));
            cp16(sK + buf * 24576 + sw, Kt + r * DFULL + s * 8);
        }
        const __half* Vt = Vg + kb * 64;
#pragma unroll
        for (int t = 0; t < 4; t++) {
            int ch = tid + t * 256;              // 0..1023
            int r = ch >> 3, s = ch & 7;
            uint32_t sw = (uint32_t)(r * 128 + ((s ^ (r & 7)) << 4));
            cp16(sV + buf * 16384 + sw, Vt + (size_t)r * SEQ + s * 8);
        }
        asm volatile("cp.async.commit_group;");
    };
    load_kv(0, 0);
    load_kv(1, 1);                       // kend >= 2 always
    asm volatile("cp.async.wait_group 1;");
    __syncthreads();

    // fragment addressing
    const int ra = lane & 15, sega = (lane >> 4) & 1;
    const uint32_t q_off = (uint32_t)((w * 16 + ra) * 384);
    const int a_swrow = ra & 7;
    const int rb = ((lane >> 4) << 3) + (lane & 7), segb = (lane >> 3) & 1;
    const int b_swrow = rb & 7;

    float m0 = -INFINITY, m1 = -INFINITY, l0 = 0.f, l1 = 0.f;
    float o[16][4];
#pragma unroll
    for (int i = 0; i < 16; i++)
#pragma unroll
        for (int e = 0; e < 4; e++) o[i][e] = 0.f;

    for (int kb = 0; kb < kend; kb++) {
        const uint32_t kbuf = sK + (kb & 1) * 24576;
        const uint32_t vbuf = sV + (kb & 1) * 16384;

        // ---- S = Q K^T (m16 x n64) ----
        float S[8][4];
#pragma unroll
        for (int j = 0; j < 8; j++)
#pragma unroll
            for (int e = 0; e < 4; e++) S[j][e] = 0.f;

#pragma unroll
        for (int ks = 0; ks < 12; ks++) {
            uint32_t a[4];
            ldsm_x4(a, sQ + q_off + (uint32_t)(((ks * 2 + sega) ^ a_swrow) << 4));
            const uint32_t bx = (uint32_t)(((ks * 2 + segb) ^ b_swrow) << 4);
#pragma unroll
            for (int nt = 0; nt < 4; nt++) {
                uint32_t b[4];
                ldsm_x4(b, kbuf + (uint32_t)((nt * 16 + rb) * 384) + bx);
                mma16816(S[nt * 2],     a, b[0], b[1]);
                mma16816(S[nt * 2 + 1], a, b[2], b[3]);
            }
        }

        // ---- causal mask (only blocks overlapping diagonal) ----
        if (kb >= 2 * qb) {
            const int row0 = qb * 128 + w * 16 + g;
            const int colb = kb * 64 + t4 * 2;
#pragma unroll
            for (int j = 0; j < 8; j++) {
#pragma unroll
                for (int e = 0; e < 2; e++) {
                    int col = colb + j * 8 + e;
                    if (col > row0) S[j][e] = -INFINITY;
                    if (col > row0 + 8) S[j][2 + e] = -INFINITY;
                }
            }
        }

        // ---- online softmax ----
        float mx0 = -INFINITY, mx1 = -INFINITY;
#pragma unroll
        for (int j = 0; j < 8; j++) {
            mx0 = fmaxf(mx0, fmaxf(S[j][0], S[j][1]));
            mx1 = fmaxf(mx1, fmaxf(S[j][2], S[j][3]));
        }
        mx0 = fmaxf(mx0, __shfl_xor_sync(0xffffffffu, mx0, 1));
        mx0 = fmaxf(mx0, __shfl_xor_sync(0xffffffffu, mx0, 2));
        mx1 = fmaxf(mx1, __shfl_xor_sync(0xffffffffu, mx1, 1));
        mx1 = fmaxf(mx1, __shfl_xor_sync(0xffffffffu, mx1, 2));
        const float mn0 = fmaxf(m0, mx0), mn1 = fmaxf(m1, mx1);
        const float c0 = __expf(m0 - mn0), c1 = __expf(m1 - mn1);
        float s0 = 0.f, s1 = 0.f;
#pragma unroll
        for (int j = 0; j < 8; j++) {
            S[j][0] = __expf(S[j][0] - mn0);
            S[j][1] = __expf(S[j][1] - mn0);
            S[j][2] = __expf(S[j][2] - mn1);
            S[j][3] = __expf(S[j][3] - mn1);
            s0 += S[j][0] + S[j][1];
            s1 += S[j][2] + S[j][3];
        }
        s0 += __shfl_xor_sync(0xffffffffu, s0, 1);
        s0 += __shfl_xor_sync(0xffffffffu, s0, 2);
        s1 += __shfl_xor_sync(0xffffffffu, s1, 1);
        s1 += __shfl_xor_sync(0xffffffffu, s1, 2);
        l0 = l0 * c0 + s0;
        l1 = l1 * c1 + s1;
        m0 = mn0; m1 = mn1;
#pragma unroll
        for (int i = 0; i < 16; i++) {
            o[i][0] *= c0; o[i][1] *= c0;
            o[i][2] *= c1; o[i][3] *= c1;
        }

        // ---- P a-fragments (fp16) ----
        uint32_t ap[4][4];
#pragma unroll
        for (int i = 0; i < 4; i++) {
            __half2 h0 = __floats2half2_rn(S[2 * i][0], S[2 * i][1]);
            __half2 h1 = __floats2half2_rn(S[2 * i][2], S[2 * i][3]);
            __half2 h2 = __floats2half2_rn(S[2 * i + 1][0], S[2 * i + 1][1]);
            __half2 h3 = __floats2half2_rn(S[2 * i + 1][2], S[2 * i + 1][3]);
            ap[i][0] = *(uint32_t*)&h0;
            ap[i][1] = *(uint32_t*)&h1;
            ap[i][2] = *(uint32_t*)&h2;
            ap[i][3] = *(uint32_t*)&h3;
        }

        // ---- O += P V ----
#pragma unroll
        for (int i = 0; i < 4; i++) {
            const uint32_t vx = (uint32_t)(((i * 2 + segb) ^ b_swrow) << 4);
#pragma unroll
            for (int nt = 0; nt < 8; nt++) {
                uint32_t b[4];
                ldsm_x4(b, vbuf + (uint32_t)((nt * 16 + rb) * 128) + vx);
                mma16816(o[nt * 2],     ap[i], b[0], b[1]);
                mma16816(o[nt * 2 + 1], ap[i], b[2], b[3]);
            }
        }

        __syncthreads();   // done reading this stage everywhere
        if (kb + 2 < kend) load_kv(kb + 2, kb & 1);
        else asm volatile("cp.async.commit_group;");
        asm volatile("cp.async.wait_group 1;");
        __syncthreads();   // stage kb+1 visible
    }

    // ---- epilogue: normalize, write fp16 ----
    const float inv0 = 1.f / l0, inv1 = 1.f / l1;
    const int r0 = qb * 128 + w * 16 + g;
#pragma unroll
    for (int nt = 0; nt < 16; nt++) {
        const int col = h * DV + nt * 8 + t4 * 2;
        __half2 lo = __floats2half2_rn(o[nt][0] * inv0, o[nt][1] * inv0);
        __half2 hi = __floats2half2_rn(o[nt][2] * inv1, o[nt][3] * inv1);
        *(__half2*)&O[(size_t)r0 * HDIM + col] = lo;
        *(__half2*)&O[(size_t)(r0 + 8) * HDIM + col] = hi;
    }
}

// ---------------- fp32 -> fp16 convert ----------------
__global__ __launch_bounds__(256) void cvt_act(
    const float* __restrict__ X, __half* __restrict__ X2, int total)
{
    int i = blockIdx.x * 256 + threadIdx.x;
    if (i >= total) return;
    X2[i] = __float2half_rn(X[i]);
}

// ---------------- weight transpose+convert: W[K,N] -> Wt[N,K] fp16 ----------------
__global__ __launch_bounds__(1024) void transpose_w_h(
    const float* __restrict__ W, __half* __restrict__ Wt, int K, int N)
{
    __shared__ float t[32][33];
    const int kb = blockIdx.x * 32, nb = blockIdx.y * 32;
    const int tx = threadIdx.x & 31, ty = threadIdx.x >> 5;
    t[ty][tx] = W[(size_t)(kb + ty) * N + nb + tx];
    __syncthreads();
    Wt[(size_t)(nb + ty) * K + kb + tx] = __float2half_rn(t[tx][ty]);
}

// ---------------- RMSNorm -> fp16 ----------------
__global__ __launch_bounds__(256) void rmsnorm_h(
    const float* __restrict__ src, const float* __restrict__ gamma,
    __half* __restrict__ dst, int stride, int len)
{
    const int row = blockIdx.x;
    const float* x = src + (size_t)row * stride;
    float ss = 0.f;
    for (int i = threadIdx.x; i < len; i += 256) { float v = x[i]; ss += v * v; }
#pragma unroll
    for (int o = 16; o; o >>= 1) ss += __shfl_xor_sync(0xffffffffu, ss, o);
    __shared__ float ws[8]; __shared__ float s_inv;
    if ((threadIdx.x & 31) == 0) ws[threadIdx.x >> 5] = ss;
    __syncthreads();
    if (threadIdx.x == 0) {
        float t = 0.f;
#pragma unroll
        for (int i = 0; i < 8; i++) t += ws[i];
        s_inv = rsqrtf(t / (float)len + 1e-6f);
    }
    __syncthreads();
    const float inv = s_inv;
    __half* out = dst + (size_t)row * len;
    for (int i = threadIdx.x; i < len; i += 256)
        out[i] = __float2half_rn(x[i] * gamma[i] * inv);
}

// ---------------- RoPE + pack -> fp16 ----------------
__global__ __launch_bounds__(192) void rope_pack_h(
    const float* __restrict__ qp, const float* __restrict__ kvp,
    const float* __restrict__ fused,
    __half* __restrict__ Q2, __half* __restrict__ K2,
    __half* __restrict__ V2)
{
    const int s = blockIdx.x, h = blockIdx.y, d = threadIdx.x;
    const float scale = 0.07216878364870323f; // 1/sqrt(192)
    float qv, kv;
    if (d < DN) {
        qv = qp[(size_t)s * QB_N + h * DFULL + d] * scale;
        kv = kvp[(size_t)s * KVB_N + h * (DN + DV) + d];
        float vv = kvp[(size_t)s * KVB_N + h * (DN + DV) + DN + d];
        V2[((size_t)h * DV + d) * SEQ + s] = __float2half_rn(vv);
    } else {
        int j = d - DN, i = j & 31;
        float inv_freq = powf(10000.f, -(float)(2 * i) / 64.f);
        float sn, cs;
        sincosf((float)s * inv_freq, &sn, &cs);
        size_t qoff = (size_t)s * QB_N + h * DFULL + DN;
        float qpe = qp[qoff + j];
        float qrot = (j < 32) ? -qp[qoff + j + 32] : qp[qoff + j - 32];
        size_t koff = (size_t)s * FUSED_NPAD + (QL + KL);
        float kpe = fused[koff + j];
        float krot = (j < 32) ? -fused[koff + j + 32] : fused[koff + j - 32];
        qv = (qpe * cs + qrot * sn) * scale;
        kv = kpe * cs + krot * sn;
    }
    Q2[((size_t)h * SEQ + s) * DFULL + d] = __float2half_rn(qv);
    K2[((size_t)h * SEQ + s) * DFULL + d] = __float2half_rn(kv);
}

// ---------------- launcher ----------------
extern "C" void kernel_launch(void* const* d_in, const int* in_sizes, int n_in,
                              void* d_out, int out_size)
{
    const float* hidden     = (const float*)d_in[0];
    const float* w_kv_a     = (const float*)d_in[1];
    const float* q_a_gamma  = (const float*)d_in[2];
    const float* w_qb       = (const float*)d_in[3];
    const float* kv_a_gamma = (const float*)d_in[4];
    const float* w_kvb      = (const float*)d_in[5];
    const float* w_o        = (const float*)d_in[6];
    float* out = (float*)d_out;

    static float *fused = nullptr, *qp, *kvp;
    static __half *H2, *QN2, *KVN2, *ATTN2, *WKVA2, *WQB2, *WKVB2, *WO2, *Q2, *K2, *V2;
    if (!fused) {
        cudaGetSymbolAddress((void**)&fused, g_fused);
        cudaGetSymbolAddress((void**)&qp,    g_qp);
        cudaGetSymbolAddress((void**)&kvp,   g_kvp);
        cudaGetSymbolAddress((void**)&H2,    g_H2);
        cudaGetSymbolAddress((void**)&QN2,   g_QN2);
        cudaGetSymbolAddress((void**)&KVN2,  g_KVN2);
        cudaGetSymbolAddress((void**)&ATTN2, g_ATTN2);
        cudaGetSymbolAddress((void**)&WKVA2, g_WKVA2);
        cudaGetSymbolAddress((void**)&WQB2,  g_WQB2);
        cudaGetSymbolAddress((void**)&WKVB2, g_WKVB2);
        cudaGetSymbolAddress((void**)&WO2,   g_WO2);
        cudaGetSymbolAddress((void**)&Q2,    g_Q2);
        cudaGetSymbolAddress((void**)&K2,    g_K2);
        cudaGetSymbolAddress((void**)&V2,    g_V2);
        cudaFuncSetAttribute(gemm_fp16, cudaFuncAttributeMaxDynamicSharedMemorySize, GSMEM);
        cudaFuncSetAttribute(flash_mma, cudaFuncAttributeMaxDynamicSharedMemorySize, FSMEM);
    }

    // operand preparation
    cvt_act<<<(SEQ * HDIM + 255) / 256, 256>>>(hidden, H2, SEQ * HDIM);
    transpose_w_h<<<dim3(HDIM / 32, FUSED_REAL / 32), 1024>>>(w_kv_a, WKVA2, HDIM, FUSED_REAL);
    transpose_w_h<<<dim3(QL / 32, QB_N / 32), 1024>>>(w_qb, WQB2, QL, QB_N);
    transpose_w_h<<<dim3(KL / 32, KVB_N / 32), 1024>>>(w_kvb, WKVB2, KL, KVB_N);
    transpose_w_h<<<dim3(HDIM / 32, HDIM / 32), 1024>>>(w_o, WO2, HDIM, HDIM);

    // 1) fused = hidden @ w_kv_a
    gemm_fp16<<<dim3(FUSED_NPAD / 128, SEQ / 128), 256, GSMEM>>>(
        H2, 0, WKVA2, 0, fused, 0, HDIM, HDIM, FUSED_NPAD, HDIM, 0);

    // 2) rmsnorm -> fp16
    rmsnorm_h<<<SEQ, 256>>>(fused, q_a_gamma, QN2, FUSED_NPAD, QL);
    rmsnorm_h<<<SEQ, 256>>>(fused + QL, kv_a_gamma, KVN2, FUSED_NPAD, KL);

    // 3) projections
    gemm_fp16<<<dim3(QB_N / 128, SEQ / 128), 256, GSMEM>>>(
        QN2, 0, WQB2, 0, qp, 0, QL, QL, QB_N, QL, 0);
    gemm_fp16<<<dim3(KVB_N / 128, SEQ / 128), 256, GSMEM>>>(
        KVN2, 0, WKVB2, 0, kvp, 0, KL, KL, KVB_N, KL, 0);

    // 4) rope + pack -> fp16
    rope_pack_h<<<dim3(SEQ, NH), 192>>>(qp, kvp, fused, Q2, K2, V2);

    // 5-7) fused causal flash attention -> fp16 ATTN2
    flash_mma<<<dim3(SEQ / 128, NH), 256, FSMEM>>>(Q2, K2, V2, ATTN2);

    // 8) out = attn @ w_o
    gemm_fp16<<<dim3(HDIM / 128, SEQ / 128), 256, GSMEM>>>(
        ATTN2, 0, WO2, 0, out, 0, HDIM, HDIM, HDIM, HDIM, 0);
}

// round 12
// speedup vs baseline: 3.0927x; 1.0661x over previous
#include <cuda_runtime.h>
#include <cuda_fp16.h>
#include <math.h>
#include <stdint.h>

#define SEQ    2048
#define HDIM   2048
#define NH     16
#define DN     128
#define DR     64
#define DV     128
#define QL     1536
#define KL     512
#define DFULL  192
#define FUSED_NPAD 2176
#define FUSED_REAL 2112
#define QB_N   3072
#define KVB_N  4096

// ---------------- device scratch (zero-initialized) ----------------
__device__ float g_fused[SEQ * FUSED_NPAD];
__device__ float g_qp[SEQ * QB_N];
__device__ float g_kvp[SEQ * KVB_N];
__device__ __half g_H2   [SEQ * HDIM];
__device__ __half g_QN2  [SEQ * QL];
__device__ __half g_KVN2 [SEQ * KL];
__device__ __half g_ATTN2[SEQ * HDIM];
__device__ __half g_WKVA2[FUSED_NPAD * HDIM];   // rows >= 2112 stay 0
__device__ __half g_WQB2 [QB_N * QL];
__device__ __half g_WKVB2[KVB_N * KL];
__device__ __half g_WO2  [HDIM * HDIM];
__device__ __half g_Q2 [NH * SEQ * DFULL];
__device__ __half g_K2 [NH * SEQ * DFULL];
__device__ __half g_V2 [NH * DV * SEQ];         // [h][d][s]

// ---------------- helpers ----------------
__device__ __forceinline__ uint32_t smem_u32(const void* p) {
    uint32_t a;
    asm("{ .reg .u64 t; cvta.to.shared.u64 t, %1; cvt.u32.u64 %0, t; }" : "=r"(a) : "l"(p));
    return a;
}
__device__ __forceinline__ void cp16(uint32_t dst, const void* src) {
    asm volatile("cp.async.cg.shared.global [%0], [%1], 16;" :: "r"(dst), "l"(src));
}
__device__ __forceinline__ void ldsm_x4(uint32_t* r, uint32_t a) {
    asm volatile("ldmatrix.sync.aligned.m8n8.x4.shared.b16 {%0,%1,%2,%3}, [%4];"
                 : "=r"(r[0]), "=r"(r[1]), "=r"(r[2]), "=r"(r[3]) : "r"(a));
}
__device__ __forceinline__ void mma16816(float* c, const uint32_t* a, uint32_t b0, uint32_t b1) {
    asm volatile(
        "mma.sync.aligned.m16n8k16.row.col.f32.f16.f16.f32 "
        "{%0,%1,%2,%3}, {%4,%5,%6,%7}, {%8,%9}, {%0,%1,%2,%3};"
        : "+f"(c[0]), "+f"(c[1]), "+f"(c[2]), "+f"(c[3])
        : "r"(a[0]), "r"(a[1]), "r"(a[2]), "r"(a[3]), "r"(b0), "r"(b1));
}

// ============================================================================
// fp16 GEMM (R10/R11 proven): C = A B^T, K-major fp16 operands, fp32 C.
// ============================================================================
#define GSMEM (3 * 32768)

__global__ __launch_bounds__(256) void gemm_fp16(
    const __half* __restrict__ A, long long sA,
    const __half* __restrict__ B, long long sB,
    float* __restrict__ C, long long sC,
    int lda, int ldb, int ldc, int K, int mode)
{
    const int n0 = blockIdx.x * 128;
    const int m0 = blockIdx.y * 128;
    if (mode == 1 && n0 > m0 + 127) return;
    A += (size_t)blockIdx.z * sA;
    B += (size_t)blockIdx.z * sB;
    C += (size_t)blockIdx.z * sC;

    int ntiles = K >> 6;
    if (mode == 2) {
        int lim = (m0 + 128) >> 6;
        if (lim < ntiles) ntiles = lim;
    }

    extern __shared__ char smraw[];
    const uint32_t s0 = smem_u32(smraw);

    const int tid = threadIdx.x;
    const int lane = tid & 31;
    const int wid = tid >> 5;
    const int wm = (wid & 1) * 64;
    const int wn = (wid >> 1) * 32;
    const int g = lane >> 2, t4 = lane & 3;

    const int ra = lane & 15;
    const int sega = (lane >> 4) & 1;
    const int rb = (lane >> 4) * 8 + (lane & 7);
    const int segb = (lane >> 3) & 1;
    uint32_t a_off[4], b_off[2];
#pragma unroll
    for (int mt = 0; mt < 4; mt++) a_off[mt] = (uint32_t)((wm + mt * 16 + ra) * 128);
#pragma unroll
    for (int p = 0; p < 2; p++) b_off[p] = (uint32_t)((wn + p * 16 + rb) * 128);
    const int a_swrow = ra & 7;
    const int b_swrow = rb & 7;

    float c[4][4][4];
#pragma unroll
    for (int i = 0; i < 4; i++)
#pragma unroll
        for (int j = 0; j < 4; j++)
#pragma unroll
            for (int e = 0; e < 4; e++) c[i][j][e] = 0.f;

    auto load_tile = [&](int i, int buf) {
        const __half* Ag = A + (size_t)m0 * lda + (i << 6);
        const __half* Bg = B + (size_t)n0 * ldb + (i << 6);
        const uint32_t da = s0 + buf * 32768;
        const uint32_t db = da + 16384;
#pragma unroll
        for (int t = 0; t < 4; t++) {
            int ch = tid + t * 256;
            int r = ch >> 3;
            int s = ch & 7;
            uint32_t sw = (uint32_t)(r * 128 + ((s ^ (r & 7)) << 4));
            cp16(da + sw, Ag + (size_t)r * lda + s * 8);
            cp16(db + sw, Bg + (size_t)r * ldb + s * 8);
        }
        asm volatile("cp.async.commit_group;");
    };

    load_tile(0, 0);
    if (ntiles > 1) load_tile(1, 1); else asm volatile("cp.async.commit_group;");

    for (int i = 0; i < ntiles; i++) {
        asm volatile("cp.async.wait_group 1;");
        __syncthreads();
        if (i + 2 < ntiles) load_tile(i + 2, (i + 2) % 3);
        else asm volatile("cp.async.commit_group;");

        const uint32_t ab = s0 + (i % 3) * 32768;
        const uint32_t bb = ab + 16384;
#pragma unroll
        for (int kc = 0; kc < 4; kc++) {
            const uint32_t ax = (uint32_t)(((kc * 2 + sega) ^ a_swrow) << 4);
            const uint32_t bx = (uint32_t)(((kc * 2 + segb) ^ b_swrow) << 4);
            uint32_t a[4][4], b[2][4];
#pragma unroll
            for (int mt = 0; mt < 4; mt++) ldsm_x4(a[mt], ab + a_off[mt] + ax);
#pragma unroll
            for (int p = 0; p < 2; p++) ldsm_x4(b[p], bb + b_off[p] + bx);
#pragma unroll
            for (int mt = 0; mt < 4; mt++) {
                mma16816(c[mt][0], a[mt], b[0][0], b[0][1]);
                mma16816(c[mt][1], a[mt], b[0][2], b[0][3]);
                mma16816(c[mt][2], a[mt], b[1][0], b[1][1]);
                mma16816(c[mt][3], a[mt], b[1][2], b[1][3]);
            }
        }
    }

#pragma unroll
    for (int mt = 0; mt < 4; mt++)
#pragma unroll
        for (int nt = 0; nt < 4; nt++) {
            int row = m0 + wm + mt * 16 + g;
            int col = n0 + wn + nt * 8 + t4 * 2;
            *(float2*)&C[(size_t)row * ldc + col] = make_float2(c[mt][nt][0], c[mt][nt][1]);
            *(float2*)&C[(size_t)(row + 8) * ldc + col] = make_float2(c[mt][nt][2], c[mt][nt][3]);
        }
}

// ============================================================================
// Fused flash attention (causal) — unchanged from R11.
// ============================================================================
#define FSMEM (49152 + 2 * 24576 + 2 * 16384)   // 131072

__global__ __launch_bounds__(256) void flash_mma(
    const __half* __restrict__ Qg_, const __half* __restrict__ Kg_,
    const __half* __restrict__ Vg_, __half* __restrict__ O)
{
    const int qb = (int)(gridDim.x - 1) - (int)blockIdx.x;  // big tiles first
    const int h = blockIdx.y;
    const int kend = 2 * qb + 2;

    extern __shared__ char sm[];
    const uint32_t sQ = smem_u32(sm);
    const uint32_t sK = sQ + 49152;
    const uint32_t sV = sK + 2 * 24576;

    const int tid = threadIdx.x, lane = tid & 31, w = tid >> 5;
    const int g = lane >> 2, t4 = lane & 3;

    const __half* Qg = Qg_ + ((size_t)h * SEQ + (size_t)qb * 128) * DFULL;
    const __half* Kg = Kg_ + (size_t)h * SEQ * DFULL;
    const __half* Vg = Vg_ + (size_t)h * DV * SEQ;

    {
#pragma unroll
        for (int t = 0; t < 12; t++) {
            int ch = tid + t * 256;
            int r = ch / 24, s = ch % 24;
            uint32_t sw = (uint32_t)(r * 384 + ((s ^ (r & 7)) << 4));
            cp16(sQ + sw, Qg + r * DFULL + s * 8);
        }
        asm volatile("cp.async.commit_group;");
    }
    auto load_kv = [&](int kb, int buf) {
        const __half* Kt = Kg + (size_t)kb * 64 * DFULL;
#pragma unroll
        for (int t = 0; t < 6; t++) {
            int ch = tid + t * 256;
            int r = ch / 24, s = ch % 24;
            uint32_t sw = (uint32_t)(r * 384 + ((s ^ (r & 7)) << 4));
            cp16(sK + buf * 24576 + sw, Kt + r * DFULL + s * 8);
        }
        const __half* Vt = Vg + kb * 64;
#pragma unroll
        for (int t = 0; t < 4; t++) {
            int ch = tid + t * 256;
            int r = ch >> 3, s = ch & 7;
            uint32_t sw = (uint32_t)(r * 128 + ((s ^ (r & 7)) << 4));
            cp16(sV + buf * 16384 + sw, Vt + (size_t)r * SEQ + s * 8);
        }
        asm volatile("cp.async.commit_group;");
    };
    load_kv(0, 0);
    load_kv(1, 1);
    asm volatile("cp.async.wait_group 1;");
    __syncthreads();

    const int ra = lane & 15, sega = (lane >> 4) & 1;
    const uint32_t q_off = (uint32_t)((w * 16 + ra) * 384);
    const int a_swrow = ra & 7;
    const int rb = ((lane >> 4) << 3) + (lane & 7), segb = (lane >> 3) & 1;
    const int b_swrow = rb & 7;

    float m0 = -INFINITY, m1 = -INFINITY, l0 = 0.f, l1 = 0.f;
    float o[16][4];
#pragma unroll
    for (int i = 0; i < 16; i++)
#pragma unroll
        for (int e = 0; e < 4; e++) o[i][e] = 0.f;

    for (int kb = 0; kb < kend; kb++) {
        const uint32_t kbuf = sK + (kb & 1) * 24576;
        const uint32_t vbuf = sV + (kb & 1) * 16384;

        float S[8][4];
#pragma unroll
        for (int j = 0; j < 8; j++)
#pragma unroll
            for (int e = 0; e < 4; e++) S[j][e] = 0.f;

#pragma unroll
        for (int ks = 0; ks < 12; ks++) {
            uint32_t a[4];
            ldsm_x4(a, sQ + q_off + (uint32_t)(((ks * 2 + sega) ^ a_swrow) << 4));
            const uint32_t bx = (uint32_t)(((ks * 2 + segb) ^ b_swrow) << 4);
#pragma unroll
            for (int nt = 0; nt < 4; nt++) {
                uint32_t b[4];
                ldsm_x4(b, kbuf + (uint32_t)((nt * 16 + rb) * 384) + bx);
                mma16816(S[nt * 2],     a, b[0], b[1]);
                mma16816(S[nt * 2 + 1], a, b[2], b[3]);
            }
        }

        if (kb >= 2 * qb) {
            const int row0 = qb * 128 + w * 16 + g;
            const int colb = kb * 64 + t4 * 2;
#pragma unroll
            for (int j = 0; j < 8; j++) {
#pragma unroll
                for (int e = 0; e < 2; e++) {
                    int col = colb + j * 8 + e;
                    if (col > row0) S[j][e] = -INFINITY;
                    if (col > row0 + 8) S[j][2 + e] = -INFINITY;
                }
            }
        }

        float mx0 = -INFINITY, mx1 = -INFINITY;
#pragma unroll
        for (int j = 0; j < 8; j++) {
            mx0 = fmaxf(mx0, fmaxf(S[j][0], S[j][1]));
            mx1 = fmaxf(mx1, fmaxf(S[j][2], S[j][3]));
        }
        mx0 = fmaxf(mx0, __shfl_xor_sync(0xffffffffu, mx0, 1));
        mx0 = fmaxf(mx0, __shfl_xor_sync(0xffffffffu, mx0, 2));
        mx1 = fmaxf(mx1, __shfl_xor_sync(0xffffffffu, mx1, 1));
        mx1 = fmaxf(mx1, __shfl_xor_sync(0xffffffffu, mx1, 2));
        const float mn0 = fmaxf(m0, mx0), mn1 = fmaxf(m1, mx1);
        const float c0 = __expf(m0 - mn0), c1 = __expf(m1 - mn1);
        float s0 = 0.f, s1 = 0.f;
#pragma unroll
        for (int j = 0; j < 8; j++) {
            S[j][0] = __expf(S[j][0] - mn0);
            S[j][1] = __expf(S[j][1] - mn0);
            S[j][2] = __expf(S[j][2] - mn1);
            S[j][3] = __expf(S[j][3] - mn1);
            s0 += S[j][0] + S[j][1];
            s1 += S[j][2] + S[j][3];
        }
        s0 += __shfl_xor_sync(0xffffffffu, s0, 1);
        s0 += __shfl_xor_sync(0xffffffffu, s0, 2);
        s1 += __shfl_xor_sync(0xffffffffu, s1, 1);
        s1 += __shfl_xor_sync(0xffffffffu, s1, 2);
        l0 = l0 * c0 + s0;
        l1 = l1 * c1 + s1;
        m0 = mn0; m1 = mn1;
#pragma unroll
        for (int i = 0; i < 16; i++) {
            o[i][0] *= c0; o[i][1] *= c0;
            o[i][2] *= c1; o[i][3] *= c1;
        }

        uint32_t ap[4][4];
#pragma unroll
        for (int i = 0; i < 4; i++) {
            __half2 h0 = __floats2half2_rn(S[2 * i][0], S[2 * i][1]);
            __half2 h1 = __floats2half2_rn(S[2 * i][2], S[2 * i][3]);
            __half2 h2 = __floats2half2_rn(S[2 * i + 1][0], S[2 * i + 1][1]);
            __half2 h3 = __floats2half2_rn(S[2 * i + 1][2], S[2 * i + 1][3]);
            ap[i][0] = *(uint32_t*)&h0;
            ap[i][1] = *(uint32_t*)&h1;
            ap[i][2] = *(uint32_t*)&h2;
            ap[i][3] = *(uint32_t*)&h3;
        }

#pragma unroll
        for (int i = 0; i < 4; i++) {
            const uint32_t vx = (uint32_t)(((i * 2 + segb) ^ b_swrow) << 4);
#pragma unroll
            for (int nt = 0; nt < 8; nt++) {
                uint32_t b[4];
                ldsm_x4(b, vbuf + (uint32_t)((nt * 16 + rb) * 128) + vx);
                mma16816(o[nt * 2],     ap[i], b[0], b[1]);
                mma16816(o[nt * 2 + 1], ap[i], b[2], b[3]);
            }
        }

        __syncthreads();
        if (kb + 2 < kend) load_kv(kb + 2, kb & 1);
        else asm volatile("cp.async.commit_group;");
        asm volatile("cp.async.wait_group 1;");
        __syncthreads();
    }

    const float inv0 = 1.f / l0, inv1 = 1.f / l1;
    const int r0 = qb * 128 + w * 16 + g;
#pragma unroll
    for (int nt = 0; nt < 16; nt++) {
        const int col = h * DV + nt * 8 + t4 * 2;
        __half2 lo = __floats2half2_rn(o[nt][0] * inv0, o[nt][1] * inv0);
        __half2 hi = __floats2half2_rn(o[nt][2] * inv1, o[nt][3] * inv1);
        *(__half2*)&O[(size_t)r0 * HDIM + col] = lo;
        *(__half2*)&O[(size_t)(r0 + 8) * HDIM + col] = hi;
    }
}

// ---------------- fp32 -> fp16 convert ----------------
__global__ __launch_bounds__(256) void cvt_act(
    const float* __restrict__ X, __half* __restrict__ X2, int total)
{
    int i = blockIdx.x * 256 + threadIdx.x;
    if (i >= total) return;
    X2[i] = __float2half_rn(X[i]);
}

// ---------------- weight transpose+convert: W[K,N] -> Wt[N,K] fp16 ----------------
__global__ __launch_bounds__(1024) void transpose_w_h(
    const float* __restrict__ W, __half* __restrict__ Wt, int K, int N)
{
    __shared__ float t[32][33];
    const int kb = blockIdx.x * 32, nb = blockIdx.y * 32;
    const int tx = threadIdx.x & 31, ty = threadIdx.x >> 5;
    t[ty][tx] = W[(size_t)(kb + ty) * N + nb + tx];
    __syncthreads();
    Wt[(size_t)(nb + ty) * K + kb + tx] = __float2half_rn(t[tx][ty]);
}

// ---------------- RMSNorm -> fp16 ----------------
__global__ __launch_bounds__(256) void rmsnorm_h(
    const float* __restrict__ src, const float* __restrict__ gamma,
    __half* __restrict__ dst, int stride, int len)
{
    const int row = blockIdx.x;
    const float* x = src + (size_t)row * stride;
    float ss = 0.f;
    for (int i = threadIdx.x; i < len; i += 256) { float v = x[i]; ss += v * v; }
#pragma unroll
    for (int o = 16; o; o >>= 1) ss += __shfl_xor_sync(0xffffffffu, ss, o);
    __shared__ float ws[8]; __shared__ float s_inv;
    if ((threadIdx.x & 31) == 0) ws[threadIdx.x >> 5] = ss;
    __syncthreads();
    if (threadIdx.x == 0) {
        float t = 0.f;
#pragma unroll
        for (int i = 0; i < 8; i++) t += ws[i];
        s_inv = rsqrtf(t / (float)len + 1e-6f);
    }
    __syncthreads();
    const float inv = s_inv;
    __half* out = dst + (size_t)row * len;
    for (int i = threadIdx.x; i < len; i += 256)
        out[i] = __float2half_rn(x[i] * gamma[i] * inv);
}

// ---------------- RoPE + pack -> fp16 ----------------
__global__ __launch_bounds__(192) void rope_pack_h(
    const float* __restrict__ qp, const float* __restrict__ kvp,
    const float* __restrict__ fused,
    __half* __restrict__ Q2, __half* __restrict__ K2,
    __half* __restrict__ V2)
{
    const int s = blockIdx.x, h = blockIdx.y, d = threadIdx.x;
    const float scale = 0.07216878364870323f; // 1/sqrt(192)
    float qv, kv;
    if (d < DN) {
        qv = qp[(size_t)s * QB_N + h * DFULL + d] * scale;
        kv = kvp[(size_t)s * KVB_N + h * (DN + DV) + d];
        float vv = kvp[(size_t)s * KVB_N + h * (DN + DV) + DN + d];
        V2[((size_t)h * DV + d) * SEQ + s] = __float2half_rn(vv);
    } else {
        int j = d - DN, i = j & 31;
        float inv_freq = powf(10000.f, -(float)(2 * i) / 64.f);
        float sn, cs;
        sincosf((float)s * inv_freq, &sn, &cs);
        size_t qoff = (size_t)s * QB_N + h * DFULL + DN;
        float qpe = qp[qoff + j];
        float qrot = (j < 32) ? -qp[qoff + j + 32] : qp[qoff + j - 32];
        size_t koff = (size_t)s * FUSED_NPAD + (QL + KL);
        float kpe = fused[koff + j];
        float krot = (j < 32) ? -fused[koff + j + 32] : fused[koff + j - 32];
        qv = (qpe * cs + qrot * sn) * scale;
        kv = kpe * cs + krot * sn;
    }
    Q2[((size_t)h * SEQ + s) * DFULL + d] = __float2half_rn(qv);
    K2[((size_t)h * SEQ + s) * DFULL + d] = __float2half_rn(kv);
}

// ---------------- launcher (multi-stream fork/join, capture-legal) ----------------
extern "C" void kernel_launch(void* const* d_in, const int* in_sizes, int n_in,
                              void* d_out, int out_size)
{
    const float* hidden     = (const float*)d_in[0];
    const float* w_kv_a     = (const float*)d_in[1];
    const float* q_a_gamma  = (const float*)d_in[2];
    const float* w_qb       = (const float*)d_in[3];
    const float* kv_a_gamma = (const float*)d_in[4];
    const float* w_kvb      = (const float*)d_in[5];
    const float* w_o        = (const float*)d_in[6];
    float* out = (float*)d_out;

    static float *fused = nullptr, *qp, *kvp;
    static __half *H2, *QN2, *KVN2, *ATTN2, *WKVA2, *WQB2, *WKVB2, *WO2, *Q2, *K2, *V2;
    static cudaStream_t sB, sC;
    static cudaEvent_t evRoot, evB, evG1, evC;
    if (!fused) {
        cudaGetSymbolAddress((void**)&fused, g_fused);
        cudaGetSymbolAddress((void**)&qp,    g_qp);
        cudaGetSymbolAddress((void**)&kvp,   g_kvp);
        cudaGetSymbolAddress((void**)&H2,    g_H2);
        cudaGetSymbolAddress((void**)&QN2,   g_QN2);
        cudaGetSymbolAddress((void**)&KVN2,  g_KVN2);
        cudaGetSymbolAddress((void**)&ATTN2, g_ATTN2);
        cudaGetSymbolAddress((void**)&WKVA2, g_WKVA2);
        cudaGetSymbolAddress((void**)&WQB2,  g_WQB2);
        cudaGetSymbolAddress((void**)&WKVB2, g_WKVB2);
        cudaGetSymbolAddress((void**)&WO2,   g_WO2);
        cudaGetSymbolAddress((void**)&Q2,    g_Q2);
        cudaGetSymbolAddress((void**)&K2,    g_K2);
        cudaGetSymbolAddress((void**)&V2,    g_V2);
        cudaFuncSetAttribute(gemm_fp16, cudaFuncAttributeMaxDynamicSharedMemorySize, GSMEM);
        cudaFuncSetAttribute(flash_mma, cudaFuncAttributeMaxDynamicSharedMemorySize, FSMEM);
        cudaStreamCreateWithFlags(&sB, cudaStreamNonBlocking);
        cudaStreamCreateWithFlags(&sC, cudaStreamNonBlocking);
        cudaEventCreateWithFlags(&evRoot, cudaEventDisableTiming);
        cudaEventCreateWithFlags(&evB,    cudaEventDisableTiming);
        cudaEventCreateWithFlags(&evG1,   cudaEventDisableTiming);
        cudaEventCreateWithFlags(&evC,    cudaEventDisableTiming);
    }

    // ---- fork: stream B does the GEMM1-independent weight transposes ----
    cudaEventRecord(evRoot, 0);
    cudaStreamWaitEvent(sB, evRoot, 0);
    transpose_w_h<<<dim3(QL / 32, QB_N / 32), 1024, 0, sB>>>(w_qb, WQB2, QL, QB_N);
    transpose_w_h<<<dim3(KL / 32, KVB_N / 32), 1024, 0, sB>>>(w_kvb, WKVB2, KL, KVB_N);
    transpose_w_h<<<dim3(HDIM / 32, HDIM / 32), 1024, 0, sB>>>(w_o, WO2, HDIM, HDIM);
    cudaEventRecord(evB, sB);

    // ---- main stream: GEMM1 critical path ----
    cvt_act<<<(SEQ * HDIM + 255) / 256, 256>>>(hidden, H2, SEQ * HDIM);
    transpose_w_h<<<dim3(HDIM / 32, FUSED_REAL / 32), 1024>>>(w_kv_a, WKVA2, HDIM, FUSED_REAL);
    gemm_fp16<<<dim3(FUSED_NPAD / 128, SEQ / 128), 256, GSMEM>>>(
        H2, 0, WKVA2, 0, fused, 0, HDIM, HDIM, FUSED_NPAD, HDIM, 0);
    cudaEventRecord(evG1, 0);

    // ---- stream C: KV branch (rmsnorm_kv -> GEMM3) ----
    cudaStreamWaitEvent(sC, evG1, 0);
    cudaStreamWaitEvent(sC, evB, 0);
    rmsnorm_h<<<SEQ, 256, 0, sC>>>(fused + QL, kv_a_gamma, KVN2, FUSED_NPAD, KL);
    gemm_fp16<<<dim3(KVB_N / 128, SEQ / 128), 256, GSMEM, sC>>>(
        KVN2, 0, WKVB2, 0, kvp, 0, KL, KL, KVB_N, KL, 0);
    cudaEventRecord(evC, sC);

    // ---- main stream: Q branch ----
    rmsnorm_h<<<SEQ, 256>>>(fused, q_a_gamma, QN2, FUSED_NPAD, QL);
    cudaStreamWaitEvent(0, evB, 0);
    gemm_fp16<<<dim3(QB_N / 128, SEQ / 128), 256, GSMEM>>>(
        QN2, 0, WQB2, 0, qp, 0, QL, QL, QB_N, QL, 0);

    // ---- join: rope needs qp (main) + kvp (stream C) ----
    cudaStreamWaitEvent(0, evC, 0);
    rope_pack_h<<<dim3(SEQ, NH), 192>>>(qp, kvp, fused, Q2, K2, V2);

    // fused causal flash attention -> fp16 ATTN2
    flash_mma<<<dim3(SEQ / 128, NH), 256, FSMEM>>>(Q2, K2, V2, ATTN2);

    // out = attn @ w_o (WO2 ready via evB wait above)
    gemm_fp16<<<dim3(HDIM / 128, SEQ / 128), 256, GSMEM>>>(
        ATTN2, 0, WO2, 0, out, 0, HDIM, HDIM, HDIM, HDIM, 0);
}

// round 13
// speedup vs baseline: 3.3844x; 1.0943x over previous
#include <cuda_runtime.h>
#include <cuda_fp16.h>
#include <math.h>
#include <stdint.h>

#define SEQ    2048
#define HDIM   2048
#define NH     16
#define DN     128
#define DR     64
#define DV     128
#define QL     1536
#define KL     512
#define DFULL  192
#define FUSED_NPAD 2176
#define FUSED_REAL 2112
#define QB_N   3072
#define KVB_N  4096

// ---------------- device scratch (zero-initialized) ----------------
__device__ float g_fused[SEQ * FUSED_NPAD];
__device__ __half g_qp[SEQ * QB_N];
__device__ __half g_kvp[SEQ * KVB_N];
__device__ __half g_H2   [SEQ * HDIM];
__device__ __half g_QN2  [SEQ * QL];
__device__ __half g_KVN2 [SEQ * KL];
__device__ __half g_ATTN2[SEQ * HDIM];
__device__ __half g_WKVA2[FUSED_NPAD * HDIM];   // rows >= 2112 stay 0
__device__ __half g_WQB2 [QB_N * QL];
__device__ __half g_WKVB2[KVB_N * KL];
__device__ __half g_WO2  [HDIM * HDIM];
__device__ __half g_Q2 [NH * SEQ * DFULL];
__device__ __half g_K2 [NH * SEQ * DFULL];
__device__ __half g_V2 [NH * DV * SEQ];         // [h][d][s]

// ---------------- helpers ----------------
__device__ __forceinline__ uint32_t smem_u32(const void* p) {
    uint32_t a;
    asm("{ .reg .u64 t; cvta.to.shared.u64 t, %1; cvt.u32.u64 %0, t; }" : "=r"(a) : "l"(p));
    return a;
}
__device__ __forceinline__ void cp16(uint32_t dst, const void* src) {
    asm volatile("cp.async.cg.shared.global [%0], [%1], 16;" :: "r"(dst), "l"(src));
}
__device__ __forceinline__ void ldsm_x4(uint32_t* r, uint32_t a) {
    asm volatile("ldmatrix.sync.aligned.m8n8.x4.shared.b16 {%0,%1,%2,%3}, [%4];"
                 : "=r"(r[0]), "=r"(r[1]), "=r"(r[2]), "=r"(r[3]) : "r"(a));
}
__device__ __forceinline__ void mma16816(float* c, const uint32_t* a, uint32_t b0, uint32_t b1) {
    asm volatile(
        "mma.sync.aligned.m16n8k16.row.col.f32.f16.f16.f32 "
        "{%0,%1,%2,%3}, {%4,%5,%6,%7}, {%8,%9}, {%0,%1,%2,%3};"
        : "+f"(c[0]), "+f"(c[1]), "+f"(c[2]), "+f"(c[3])
        : "r"(a[0]), "r"(a[1]), "r"(a[2]), "r"(a[3]), "r"(b0), "r"(b1));
}

// ============================================================================
// fp16 GEMM: C = A B^T, K-major fp16 operands; fp32 or fp16 C (outHalf).
// ============================================================================
#define GSMEM (3 * 32768)

__global__ __launch_bounds__(256) void gemm_fp16(
    const __half* __restrict__ A, long long sA,
    const __half* __restrict__ B, long long sB,
    float* __restrict__ C, long long sC,
    int lda, int ldb, int ldc, int K, int mode, int outHalf)
{
    const int n0 = blockIdx.x * 128;
    const int m0 = blockIdx.y * 128;
    if (mode == 1 && n0 > m0 + 127) return;
    A += (size_t)blockIdx.z * sA;
    B += (size_t)blockIdx.z * sB;
    C += (size_t)blockIdx.z * sC;

    int ntiles = K >> 6;
    if (mode == 2) {
        int lim = (m0 + 128) >> 6;
        if (lim < ntiles) ntiles = lim;
    }

    extern __shared__ char smraw[];
    const uint32_t s0 = smem_u32(smraw);

    const int tid = threadIdx.x;
    const int lane = tid & 31;
    const int wid = tid >> 5;
    const int wm = (wid & 1) * 64;
    const int wn = (wid >> 1) * 32;
    const int g = lane >> 2, t4 = lane & 3;

    const int ra = lane & 15;
    const int sega = (lane >> 4) & 1;
    const int rb = (lane >> 4) * 8 + (lane & 7);
    const int segb = (lane >> 3) & 1;
    uint32_t a_off[4], b_off[2];
#pragma unroll
    for (int mt = 0; mt < 4; mt++) a_off[mt] = (uint32_t)((wm + mt * 16 + ra) * 128);
#pragma unroll
    for (int p = 0; p < 2; p++) b_off[p] = (uint32_t)((wn + p * 16 + rb) * 128);
    const int a_swrow = ra & 7;
    const int b_swrow = rb & 7;

    float c[4][4][4];
#pragma unroll
    for (int i = 0; i < 4; i++)
#pragma unroll
        for (int j = 0; j < 4; j++)
#pragma unroll
            for (int e = 0; e < 4; e++) c[i][j][e] = 0.f;

    auto load_tile = [&](int i, int buf) {
        const __half* Ag = A + (size_t)m0 * lda + (i << 6);
        const __half* Bg = B + (size_t)n0 * ldb + (i << 6);
        const uint32_t da = s0 + buf * 32768;
        const uint32_t db = da + 16384;
#pragma unroll
        for (int t = 0; t < 4; t++) {
            int ch = tid + t * 256;
            int r = ch >> 3;
            int s = ch & 7;
            uint32_t sw = (uint32_t)(r * 128 + ((s ^ (r & 7)) << 4));
            cp16(da + sw, Ag + (size_t)r * lda + s * 8);
            cp16(db + sw, Bg + (size_t)r * ldb + s * 8);
        }
        asm volatile("cp.async.commit_group;");
    };

    load_tile(0, 0);
    if (ntiles > 1) load_tile(1, 1); else asm volatile("cp.async.commit_group;");

    for (int i = 0; i < ntiles; i++) {
        asm volatile("cp.async.wait_group 1;");
        __syncthreads();
        if (i + 2 < ntiles) load_tile(i + 2, (i + 2) % 3);
        else asm volatile("cp.async.commit_group;");

        const uint32_t ab = s0 + (i % 3) * 32768;
        const uint32_t bb = ab + 16384;
#pragma unroll
        for (int kc = 0; kc < 4; kc++) {
            const uint32_t ax = (uint32_t)(((kc * 2 + sega) ^ a_swrow) << 4);
            const uint32_t bx = (uint32_t)(((kc * 2 + segb) ^ b_swrow) << 4);
            uint32_t a[4][4], b[2][4];
#pragma unroll
            for (int mt = 0; mt < 4; mt++) ldsm_x4(a[mt], ab + a_off[mt] + ax);
#pragma unroll
            for (int p = 0; p < 2; p++) ldsm_x4(b[p], bb + b_off[p] + bx);
#pragma unroll
            for (int mt = 0; mt < 4; mt++) {
                mma16816(c[mt][0], a[mt], b[0][0], b[0][1]);
                mma16816(c[mt][1], a[mt], b[0][2], b[0][3]);
                mma16816(c[mt][2], a[mt], b[1][0], b[1][1]);
                mma16816(c[mt][3], a[mt], b[1][2], b[1][3]);
            }
        }
    }

    if (outHalf) {
        __half* Ch = (__half*)C;
#pragma unroll
        for (int mt = 0; mt < 4; mt++)
#pragma unroll
            for (int nt = 0; nt < 4; nt++) {
                int row = m0 + wm + mt * 16 + g;
                int col = n0 + wn + nt * 8 + t4 * 2;
                __half2 lo = __floats2half2_rn(c[mt][nt][0], c[mt][nt][1]);
                __half2 hi = __floats2half2_rn(c[mt][nt][2], c[mt][nt][3]);
                *(__half2*)&Ch[(size_t)row * ldc + col] = lo;
                *(__half2*)&Ch[(size_t)(row + 8) * ldc + col] = hi;
            }
    } else {
#pragma unroll
        for (int mt = 0; mt < 4; mt++)
#pragma unroll
            for (int nt = 0; nt < 4; nt++) {
                int row = m0 + wm + mt * 16 + g;
                int col = n0 + wn + nt * 8 + t4 * 2;
                *(float2*)&C[(size_t)row * ldc + col] = make_float2(c[mt][nt][0], c[mt][nt][1]);
                *(float2*)&C[(size_t)(row + 8) * ldc + col] = make_float2(c[mt][nt][2], c[mt][nt][3]);
            }
    }
}

// ============================================================================
// Fused flash attention (causal) — unchanged from R11/R12.
// ============================================================================
#define FSMEM (49152 + 2 * 24576 + 2 * 16384)   // 131072

__global__ __launch_bounds__(256) void flash_mma(
    const __half* __restrict__ Qg_, const __half* __restrict__ Kg_,
    const __half* __restrict__ Vg_, __half* __restrict__ O)
{
    const int qb = (int)(gridDim.x - 1) - (int)blockIdx.x;  // big tiles first
    const int h = blockIdx.y;
    const int kend = 2 * qb + 2;

    extern __shared__ char sm[];
    const uint32_t sQ = smem_u32(sm);
    const uint32_t sK = sQ + 49152;
    const uint32_t sV = sK + 2 * 24576;

    const int tid = threadIdx.x, lane = tid & 31, w = tid >> 5;
    const int g = lane >> 2, t4 = lane & 3;

    const __half* Qg = Qg_ + ((size_t)h * SEQ + (size_t)qb * 128) * DFULL;
    const __half* Kg = Kg_ + (size_t)h * SEQ * DFULL;
    const __half* Vg = Vg_ + (size_t)h * DV * SEQ;

    {
#pragma unroll
        for (int t = 0; t < 12; t++) {
            int ch = tid + t * 256;
            int r = ch / 24, s = ch % 24;
            uint32_t sw = (uint32_t)(r * 384 + ((s ^ (r & 7)) << 4));
            cp16(sQ + sw, Qg + r * DFULL + s * 8);
        }
        asm volatile("cp.async.commit_group;");
    }
    auto load_kv = [&](int kb, int buf) {
        const __half* Kt = Kg + (size_t)kb * 64 * DFULL;
#pragma unroll
        for (int t = 0; t < 6; t++) {
            int ch = tid + t * 256;
            int r = ch / 24, s = ch % 24;
            uint32_t sw = (uint32_t)(r * 384 + ((s ^ (r & 7)) << 4));
            cp16(sK + buf * 24576 + sw, Kt + r * DFULL + s * 8);
        }
        const __half* Vt = Vg + kb * 64;
#pragma unroll
        for (int t = 0; t < 4; t++) {
            int ch = tid + t * 256;
            int r = ch >> 3, s = ch & 7;
            uint32_t sw = (uint32_t)(r * 128 + ((s ^ (r & 7)) << 4));
            cp16(sV + buf * 16384 + sw, Vt + (size_t)r * SEQ + s * 8);
        }
        asm volatile("cp.async.commit_group;");
    };
    load_kv(0, 0);
    load_kv(1, 1);
    asm volatile("cp.async.wait_group 1;");
    __syncthreads();

    const int ra = lane & 15, sega = (lane >> 4) & 1;
    const uint32_t q_off = (uint32_t)((w * 16 + ra) * 384);
    const int a_swrow = ra & 7;
    const int rb = ((lane >> 4) << 3) + (lane & 7), segb = (lane >> 3) & 1;
    const int b_swrow = rb & 7;

    float m0 = -INFINITY, m1 = -INFINITY, l0 = 0.f, l1 = 0.f;
    float o[16][4];
#pragma unroll
    for (int i = 0; i < 16; i++)
#pragma unroll
        for (int e = 0; e < 4; e++) o[i][e] = 0.f;

    for (int kb = 0; kb < kend; kb++) {
        const uint32_t kbuf = sK + (kb & 1) * 24576;
        const uint32_t vbuf = sV + (kb & 1) * 16384;

        float S[8][4];
#pragma unroll
        for (int j = 0; j < 8; j++)
#pragma unroll
            for (int e = 0; e < 4; e++) S[j][e] = 0.f;

#pragma unroll
        for (int ks = 0; ks < 12; ks++) {
            uint32_t a[4];
            ldsm_x4(a, sQ + q_off + (uint32_t)(((ks * 2 + sega) ^ a_swrow) << 4));
            const uint32_t bx = (uint32_t)(((ks * 2 + segb) ^ b_swrow) << 4);
#pragma unroll
            for (int nt = 0; nt < 4; nt++) {
                uint32_t b[4];
                ldsm_x4(b, kbuf + (uint32_t)((nt * 16 + rb) * 384) + bx);
                mma16816(S[nt * 2],     a, b[0], b[1]);
                mma16816(S[nt * 2 + 1], a, b[2], b[3]);
            }
        }

        if (kb >= 2 * qb) {
            const int row0 = qb * 128 + w * 16 + g;
            const int colb = kb * 64 + t4 * 2;
#pragma unroll
            for (int j = 0; j < 8; j++) {
#pragma unroll
                for (int e = 0; e < 2; e++) {
                    int col = colb + j * 8 + e;
                    if (col > row0) S[j][e] = -INFINITY;
                    if (col > row0 + 8) S[j][2 + e] = -INFINITY;
                }
            }
        }

        float mx0 = -INFINITY, mx1 = -INFINITY;
#pragma unroll
        for (int j = 0; j < 8; j++) {
            mx0 = fmaxf(mx0, fmaxf(S[j][0], S[j][1]));
            mx1 = fmaxf(mx1, fmaxf(S[j][2], S[j][3]));
        }
        mx0 = fmaxf(mx0, __shfl_xor_sync(0xffffffffu, mx0, 1));
        mx0 = fmaxf(mx0, __shfl_xor_sync(0xffffffffu, mx0, 2));
        mx1 = fmaxf(mx1, __shfl_xor_sync(0xffffffffu, mx1, 1));
        mx1 = fmaxf(mx1, __shfl_xor_sync(0xffffffffu, mx1, 2));
        const float mn0 = fmaxf(m0, mx0), mn1 = fmaxf(m1, mx1);
        const float c0 = __expf(m0 - mn0), c1 = __expf(m1 - mn1);
        float s0 = 0.f, s1 = 0.f;
#pragma unroll
        for (int j = 0; j < 8; j++) {
            S[j][0] = __expf(S[j][0] - mn0);
            S[j][1] = __expf(S[j][1] - mn0);
            S[j][2] = __expf(S[j][2] - mn1);
            S[j][3] = __expf(S[j][3] - mn1);
            s0 += S[j][0] + S[j][1];
            s1 += S[j][2] + S[j][3];
        }
        s0 += __shfl_xor_sync(0xffffffffu, s0, 1);
        s0 += __shfl_xor_sync(0xffffffffu, s0, 2);
        s1 += __shfl_xor_sync(0xffffffffu, s1, 1);
        s1 += __shfl_xor_sync(0xffffffffu, s1, 2);
        l0 = l0 * c0 + s0;
        l1 = l1 * c1 + s1;
        m0 = mn0; m1 = mn1;
#pragma unroll
        for (int i = 0; i < 16; i++) {
            o[i][0] *= c0; o[i][1] *= c0;
            o[i][2] *= c1; o[i][3] *= c1;
        }

        uint32_t ap[4][4];
#pragma unroll
        for (int i = 0; i < 4; i++) {
            __half2 h0 = __floats2half2_rn(S[2 * i][0], S[2 * i][1]);
            __half2 h1 = __floats2half2_rn(S[2 * i][2], S[2 * i][3]);
            __half2 h2 = __floats2half2_rn(S[2 * i + 1][0], S[2 * i + 1][1]);
            __half2 h3 = __floats2half2_rn(S[2 * i + 1][2], S[2 * i + 1][3]);
            ap[i][0] = *(uint32_t*)&h0;
            ap[i][1] = *(uint32_t*)&h1;
            ap[i][2] = *(uint32_t*)&h2;
            ap[i][3] = *(uint32_t*)&h3;
        }

#pragma unroll
        for (int i = 0; i < 4; i++) {
            const uint32_t vx = (uint32_t)(((i * 2 + segb) ^ b_swrow) << 4);
#pragma unroll
            for (int nt = 0; nt < 8; nt++) {
                uint32_t b[4];
                ldsm_x4(b, vbuf + (uint32_t)((nt * 16 + rb) * 128) + vx);
                mma16816(o[nt * 2],     ap[i], b[0], b[1]);
                mma16816(o[nt * 2 + 1], ap[i], b[2], b[3]);
            }
        }

        __syncthreads();
        if (kb + 2 < kend) load_kv(kb + 2, kb & 1);
        else asm volatile("cp.async.commit_group;");
        asm volatile("cp.async.wait_group 1;");
        __syncthreads();
    }

    const float inv0 = 1.f / l0, inv1 = 1.f / l1;
    const int r0 = qb * 128 + w * 16 + g;
#pragma unroll
    for (int nt = 0; nt < 16; nt++) {
        const int col = h * DV + nt * 8 + t4 * 2;
        __half2 lo = __floats2half2_rn(o[nt][0] * inv0, o[nt][1] * inv0);
        __half2 hi = __floats2half2_rn(o[nt][2] * inv1, o[nt][3] * inv1);
        *(__half2*)&O[(size_t)r0 * HDIM + col] = lo;
        *(__half2*)&O[(size_t)(r0 + 8) * HDIM + col] = hi;
    }
}

// ---------------- fp32 -> fp16 convert (vectorized, 4/thread) ----------------
__global__ __launch_bounds__(256) void cvt_act4(
    const float4* __restrict__ X, uint2* __restrict__ X2, int total4)
{
    int i = blockIdx.x * 256 + threadIdx.x;
    if (i >= total4) return;
    float4 v = X[i];
    __half2 a = __floats2half2_rn(v.x, v.y);
    __half2 b = __floats2half2_rn(v.z, v.w);
    uint2 o;
    o.x = *(uint32_t*)&a;
    o.y = *(uint32_t*)&b;
    X2[i] = o;
}

// ---------------- weight transpose+convert (vectorized): W[K,N] -> Wt[N,K] fp16 ----------------
__global__ __launch_bounds__(256) void transpose_w_h(
    const float* __restrict__ W, __half* __restrict__ Wt, int K, int N)
{
    __shared__ __half tt[32][40];   // [n][k], 80B row stride (8B-aligned vectors)
    const int kb = blockIdx.x * 32, nb = blockIdx.y * 32;
    const int tx = threadIdx.x & 7, ty = threadIdx.x >> 3;   // ty: 0..31
    float4 v = *(const float4*)&W[(size_t)(kb + ty) * N + nb + tx * 4];
    tt[tx * 4 + 0][ty] = __float2half_rn(v.x);
    tt[tx * 4 + 1][ty] = __float2half_rn(v.y);
    tt[tx * 4 + 2][ty] = __float2half_rn(v.z);
    tt[tx * 4 + 3][ty] = __float2half_rn(v.w);
    __syncthreads();
    uint2 o;
    __half2 a, b;
    a.x = tt[ty][tx * 4 + 0]; a.y = tt[ty][tx * 4 + 1];
    b.x = tt[ty][tx * 4 + 2]; b.y = tt[ty][tx * 4 + 3];
    o.x = *(uint32_t*)&a;
    o.y = *(uint32_t*)&b;
    *(uint2*)&Wt[(size_t)(nb + ty) * K + kb + tx * 4] = o;
}

// ---------------- RMSNorm -> fp16 ----------------
__global__ __launch_bounds__(256) void rmsnorm_h(
    const float* __restrict__ src, const float* __restrict__ gamma,
    __half* __restrict__ dst, int stride, int len)
{
    const int row = blockIdx.x;
    const float* x = src + (size_t)row * stride;
    float ss = 0.f;
    for (int i = threadIdx.x; i < len; i += 256) { float v = x[i]; ss += v * v; }
#pragma unroll
    for (int o = 16; o; o >>= 1) ss += __shfl_xor_sync(0xffffffffu, ss, o);
    __shared__ float ws[8]; __shared__ float s_inv;
    if ((threadIdx.x & 31) == 0) ws[threadIdx.x >> 5] = ss;
    __syncthreads();
    if (threadIdx.x == 0) {
        float t = 0.f;
#pragma unroll
        for (int i = 0; i < 8; i++) t += ws[i];
        s_inv = rsqrtf(t / (float)len + 1e-6f);
    }
    __syncthreads();
    const float inv = s_inv;
    __half* out = dst + (size_t)row * len;
    for (int i = threadIdx.x; i < len; i += 256)
        out[i] = __float2half_rn(x[i] * gamma[i] * inv);
}

// ---------------- RoPE + pack -> fp16 (qp/kvp now fp16) ----------------
__global__ __launch_bounds__(192) void rope_pack_h(
    const __half* __restrict__ qp, const __half* __restrict__ kvp,
    const float* __restrict__ fused,
    __half* __restrict__ Q2, __half* __restrict__ K2,
    __half* __restrict__ V2)
{
    const int s = blockIdx.x, h = blockIdx.y, d = threadIdx.x;
    const float scale = 0.07216878364870323f; // 1/sqrt(192)
    float qv, kv;
    if (d < DN) {
        qv = __half2float(qp[(size_t)s * QB_N + h * DFULL + d]) * scale;
        kv = __half2float(kvp[(size_t)s * KVB_N + h * (DN + DV) + d]);
        V2[((size_t)h * DV + d) * SEQ + s] = kvp[(size_t)s * KVB_N + h * (DN + DV) + DN + d];
    } else {
        int j = d - DN, i = j & 31;
        float inv_freq = powf(10000.f, -(float)(2 * i) / 64.f);
        float sn, cs;
        sincosf((float)s * inv_freq, &sn, &cs);
        size_t qoff = (size_t)s * QB_N + h * DFULL + DN;
        float qpe = __half2float(qp[qoff + j]);
        float qrot = (j < 32) ? -__half2float(qp[qoff + j + 32])
                              :  __half2float(qp[qoff + j - 32]);
        size_t koff = (size_t)s * FUSED_NPAD + (QL + KL);
        float kpe = fused[koff + j];
        float krot = (j < 32) ? -fused[koff + j + 32] : fused[koff + j - 32];
        qv = (qpe * cs + qrot * sn) * scale;
        kv = kpe * cs + krot * sn;
    }
    Q2[((size_t)h * SEQ + s) * DFULL + d] = __float2half_rn(qv);
    K2[((size_t)h * SEQ + s) * DFULL + d] = __float2half_rn(kv);
}

// ---------------- launcher (multi-stream fork/join, capture-legal) ----------------
extern "C" void kernel_launch(void* const* d_in, const int* in_sizes, int n_in,
                              void* d_out, int out_size)
{
    const float* hidden     = (const float*)d_in[0];
    const float* w_kv_a     = (const float*)d_in[1];
    const float* q_a_gamma  = (const float*)d_in[2];
    const float* w_qb       = (const float*)d_in[3];
    const float* kv_a_gamma = (const float*)d_in[4];
    const float* w_kvb      = (const float*)d_in[5];
    const float* w_o        = (const float*)d_in[6];
    float* out = (float*)d_out;

    static float* fused = nullptr;
    static __half *qp, *kvp, *H2, *QN2, *KVN2, *ATTN2, *WKVA2, *WQB2, *WKVB2, *WO2, *Q2, *K2, *V2;
    static cudaStream_t sB, sC;
    static cudaEvent_t evRoot, evB, evG1, evC;
    if (!fused) {
        cudaGetSymbolAddress((void**)&fused, g_fused);
        cudaGetSymbolAddress((void**)&qp,    g_qp);
        cudaGetSymbolAddress((void**)&kvp,   g_kvp);
        cudaGetSymbolAddress((void**)&H2,    g_H2);
        cudaGetSymbolAddress((void**)&QN2,   g_QN2);
        cudaGetSymbolAddress((void**)&KVN2,  g_KVN2);
        cudaGetSymbolAddress((void**)&ATTN2, g_ATTN2);
        cudaGetSymbolAddress((void**)&WKVA2, g_WKVA2);
        cudaGetSymbolAddress((void**)&WQB2,  g_WQB2);
        cudaGetSymbolAddress((void**)&WKVB2, g_WKVB2);
        cudaGetSymbolAddress((void**)&WO2,   g_WO2);
        cudaGetSymbolAddress((void**)&Q2,    g_Q2);
        cudaGetSymbolAddress((void**)&K2,    g_K2);
        cudaGetSymbolAddress((void**)&V2,    g_V2);
        cudaFuncSetAttribute(gemm_fp16, cudaFuncAttributeMaxDynamicSharedMemorySize, GSMEM);
        cudaFuncSetAttribute(flash_mma, cudaFuncAttributeMaxDynamicSharedMemorySize, FSMEM);
        cudaStreamCreateWithFlags(&sB, cudaStreamNonBlocking);
        cudaStreamCreateWithFlags(&sC, cudaStreamNonBlocking);
        cudaEventCreateWithFlags(&evRoot, cudaEventDisableTiming);
        cudaEventCreateWithFlags(&evB,    cudaEventDisableTiming);
        cudaEventCreateWithFlags(&evG1,   cudaEventDisableTiming);
        cudaEventCreateWithFlags(&evC,    cudaEventDisableTiming);
    }

    // ---- fork: stream B does the GEMM1-independent weight transposes ----
    cudaEventRecord(evRoot, 0);
    cudaStreamWaitEvent(sB, evRoot, 0);
    transpose_w_h<<<dim3(QL / 32, QB_N / 32), 256, 0, sB>>>(w_qb, WQB2, QL, QB_N);
    transpose_w_h<<<dim3(KL / 32, KVB_N / 32), 256, 0, sB>>>(w_kvb, WKVB2, KL, KVB_N);
    transpose_w_h<<<dim3(HDIM / 32, HDIM / 32), 256, 0, sB>>>(w_o, WO2, HDIM, HDIM);
    cudaEventRecord(evB, sB);

    // ---- main stream: GEMM1 critical path ----
    cvt_act4<<<(SEQ * HDIM / 4 + 255) / 256, 256>>>(
        (const float4*)hidden, (uint2*)H2, SEQ * HDIM / 4);
    transpose_w_h<<<dim3(HDIM / 32, FUSED_REAL / 32), 256>>>(w_kv_a, WKVA2, HDIM, FUSED_REAL);
    gemm_fp16<<<dim3(FUSED_NPAD / 128, SEQ / 128), 256, GSMEM>>>(
        H2, 0, WKVA2, 0, fused, 0, HDIM, HDIM, FUSED_NPAD, HDIM, 0, 0);
    cudaEventRecord(evG1, 0);

    // ---- stream C: KV branch (rmsnorm_kv -> GEMM3, fp16 out) ----
    cudaStreamWaitEvent(sC, evG1, 0);
    cudaStreamWaitEvent(sC, evB, 0);
    rmsnorm_h<<<SEQ, 256, 0, sC>>>(fused + QL, kv_a_gamma, KVN2, FUSED_NPAD, KL);
    gemm_fp16<<<dim3(KVB_N / 128, SEQ / 128), 256, GSMEM, sC>>>(
        KVN2, 0, WKVB2, 0, (float*)kvp, 0, KL, KL, KVB_N, KL, 0, 1);
    cudaEventRecord(evC, sC);

    // ---- main stream: Q branch (fp16 out) ----
    rmsnorm_h<<<SEQ, 256>>>(fused, q_a_gamma, QN2, FUSED_NPAD, QL);
    cudaStreamWaitEvent(0, evB, 0);
    gemm_fp16<<<dim3(QB_N / 128, SEQ / 128), 256, GSMEM>>>(
        QN2, 0, WQB2, 0, (float*)qp, 0, QL, QL, QB_N, QL, 0, 1);

    // ---- join: rope needs qp (main) + kvp (stream C) ----
    cudaStreamWaitEvent(0, evC, 0);
    rope_pack_h<<<dim3(SEQ, NH), 192>>>(qp, kvp, fused, Q2, K2, V2);

    // fused causal flash attention -> fp16 ATTN2
    flash_mma<<<dim3(SEQ / 128, NH), 256, FSMEM>>>(Q2, K2, V2, ATTN2);

    // out = attn @ w_o (WO2 ready via evB wait above)
    gemm_fp16<<<dim3(HDIM / 128, SEQ / 128), 256, GSMEM>>>(
        ATTN2, 0, WO2, 0, out, 0, HDIM, HDIM, HDIM, HDIM, 0, 0);
}